// round 1
// baseline (speedup 1.0000x reference)
#include <cuda_runtime.h>
#include <cuda_bf16.h>
#include <math_constants.h>

// Problem constants
#define Bc 2
#define Sc 2048
#define Ec 1024
#define Hc 16
#define Dc 64
#define M_TOK (Bc * Sc)          // 4096 rows

// Scratch (no cudaMalloc allowed)
__device__ float g_qkv[(size_t)Bc * Sc * 3 * Ec];   // [B,S,3E]  ~50 MB
__device__ float g_attn[(size_t)Bc * Sc * Ec];      // [B,S,E]   ~17 MB

// ---------------------------------------------------------------------------
// SGEMM + bias:  C[M,N] = A[M,K] @ B[K,N] + bias[N]
// BM=BN=128, BK=16, 256 threads, 8x8 per-thread tile.
// Requires M%128==0, N%128==0, K%16==0 (true for all our shapes).
// ---------------------------------------------------------------------------
__global__ __launch_bounds__(256)
void sgemm_bias(const float* __restrict__ A, const float* __restrict__ B,
                const float* __restrict__ bias, float* __restrict__ C,
                int M, int N, int K)
{
    const int BM = 128, BN = 128, BK = 16;
    __shared__ float As[BK][BM + 4];   // row base 132 floats = 528B (16B aligned)
    __shared__ float Bs[BK][BN + 4];

    const int tid = threadIdx.x;
    const int bm = blockIdx.y * BM;
    const int bn = blockIdx.x * BN;
    const int tx = tid & 15;   // N direction
    const int ty = tid >> 4;   // M direction

    float acc[8][8];
#pragma unroll
    for (int i = 0; i < 8; i++)
#pragma unroll
        for (int j = 0; j < 8; j++) acc[i][j] = 0.f;

    for (int k0 = 0; k0 < K; k0 += BK) {
        // Load A tile (transposed into As[k][m]). 512 float4 total, 2 per thread.
#pragma unroll
        for (int it = 0; it < 2; it++) {
            int idx = tid + it * 256;         // 0..511
            int row = idx >> 2;               // 0..127
            int kk4 = (idx & 3) * 4;          // 0,4,8,12
            float4 v = *(const float4*)&A[(size_t)(bm + row) * K + k0 + kk4];
            As[kk4 + 0][row] = v.x;
            As[kk4 + 1][row] = v.y;
            As[kk4 + 2][row] = v.z;
            As[kk4 + 3][row] = v.w;
        }
        // Load B tile. 512 float4 total, 2 per thread, coalesced.
#pragma unroll
        for (int it = 0; it < 2; it++) {
            int idx = tid + it * 256;
            int kk = idx >> 5;                // 0..15
            int nn = (idx & 31) * 4;
            float4 v = *(const float4*)&B[(size_t)(k0 + kk) * N + bn + nn];
            *(float4*)&Bs[kk][nn] = v;
        }
        __syncthreads();

#pragma unroll
        for (int kk = 0; kk < BK; kk++) {
            float a[8], b[8];
#pragma unroll
            for (int i = 0; i < 8; i++) a[i] = As[kk][ty * 8 + i];
#pragma unroll
            for (int j = 0; j < 8; j++) b[j] = Bs[kk][tx * 8 + j];
#pragma unroll
            for (int i = 0; i < 8; i++)
#pragma unroll
                for (int j = 0; j < 8; j++)
                    acc[i][j] += a[i] * b[j];
        }
        __syncthreads();
    }

#pragma unroll
    for (int i = 0; i < 8; i++) {
        int row = bm + ty * 8 + i;
#pragma unroll
        for (int j = 0; j < 8; j += 4) {
            int col = bn + tx * 8 + j;
            float4 o;
            o.x = acc[i][j + 0] + bias[col + 0];
            o.y = acc[i][j + 1] + bias[col + 1];
            o.z = acc[i][j + 2] + bias[col + 2];
            o.w = acc[i][j + 3] + bias[col + 3];
            *(float4*)&C[(size_t)row * N + col] = o;
        }
    }
}

// ---------------------------------------------------------------------------
// Flash-style causal attention, fp32.
// Grid: (S/128, H, B). Block: 128 threads; thread t owns query row qt*128+t.
// K/V tiles of 64 rows in smem; Q row + O accumulator in registers.
// ---------------------------------------------------------------------------
__global__ __launch_bounds__(128)
void attn_kernel(const float* __restrict__ qkv, float* __restrict__ out)
{
    const int qt = blockIdx.x;
    const int h  = blockIdx.y;
    const int b  = blockIdx.z;
    const int tid = threadIdx.x;
    const int q_idx = qt * 128 + tid;

    __shared__ float Ks[64][68];   // 68-pad: 272B row stride, 16B aligned
    __shared__ float Vs[64][68];

    // Load Q row into registers
    float q[Dc];
    {
        const float* qptr = qkv + ((size_t)(b * Sc + q_idx)) * (3 * Ec) + h * Dc;
#pragma unroll
        for (int d = 0; d < Dc; d += 4) {
            float4 v = *(const float4*)(qptr + d);
            q[d] = v.x; q[d + 1] = v.y; q[d + 2] = v.z; q[d + 3] = v.w;
        }
    }

    float accO[Dc];
#pragma unroll
    for (int d = 0; d < Dc; d++) accO[d] = 0.f;
    float m = -1e30f;
    float l = 0.f;

    const int n_tiles = 2 * (qt + 1);          // keys 0 .. qt*128+127
    const float scale = 0.125f;                // 1/sqrt(64)

    float s[64];                               // per-thread scores (local mem ok)

    for (int kt = 0; kt < n_tiles; kt++) {
        const int k0 = kt * 64;
        __syncthreads();
        // threads 0-63 load K rows, 64-127 load V rows (64 floats each)
        {
            int r = tid & 63;
            const float* src = qkv + ((size_t)(b * Sc + k0 + r)) * (3 * Ec)
                               + ((tid < 64) ? Ec : 2 * Ec) + h * Dc;
            float* dst = (tid < 64) ? &Ks[r][0] : &Vs[r][0];
#pragma unroll
            for (int d = 0; d < Dc; d += 4) {
                *(float4*)(dst + d) = *(const float4*)(src + d);
            }
        }
        __syncthreads();

        // scores: s[j] = (q . K[j]) * scale
        const bool need_mask = (k0 + 63 > q_idx);
#pragma unroll 8
        for (int j = 0; j < 64; j++) {
            float sum = 0.f;
#pragma unroll
            for (int d4 = 0; d4 < 16; d4++) {
                float4 kv = *(const float4*)&Ks[j][d4 * 4];
                sum += q[d4 * 4 + 0] * kv.x;
                sum += q[d4 * 4 + 1] * kv.y;
                sum += q[d4 * 4 + 2] * kv.z;
                sum += q[d4 * 4 + 3] * kv.w;
            }
            sum *= scale;
            if (need_mask && (k0 + j > q_idx)) sum = -1e30f;
            s[j] = sum;
        }

        // tile max
        float tmax = -1e30f;
#pragma unroll 16
        for (int j = 0; j < 64; j++) tmax = fmaxf(tmax, s[j]);

        float mnew = fmaxf(m, tmax);
        float corr = __expf(m - mnew);
        l *= corr;
#pragma unroll
        for (int d = 0; d < Dc; d++) accO[d] *= corr;
        m = mnew;

        // p = exp(s - m); accumulate into O
#pragma unroll 8
        for (int j = 0; j < 64; j++) {
            float p = __expf(s[j] - mnew);
            l += p;
#pragma unroll
            for (int d4 = 0; d4 < 16; d4++) {
                float4 vv = *(const float4*)&Vs[j][d4 * 4];
                accO[d4 * 4 + 0] += p * vv.x;
                accO[d4 * 4 + 1] += p * vv.y;
                accO[d4 * 4 + 2] += p * vv.z;
                accO[d4 * 4 + 3] += p * vv.w;
            }
        }
    }

    // write out merged-head layout [B,S,E]
    {
        float inv = 1.f / l;
        float* optr = out + ((size_t)(b * Sc + q_idx)) * Ec + h * Dc;
#pragma unroll
        for (int d = 0; d < Dc; d += 4) {
            float4 o;
            o.x = accO[d + 0] * inv;
            o.y = accO[d + 1] * inv;
            o.z = accO[d + 2] * inv;
            o.w = accO[d + 3] * inv;
            *(float4*)(optr + d) = o;
        }
    }
}

// ---------------------------------------------------------------------------
extern "C" void kernel_launch(void* const* d_in, const int* in_sizes, int n_in,
                              void* d_out, int out_size)
{
    const float* x  = (const float*)d_in[0];   // hidden_states [B,S,E]
    const float* wa = (const float*)d_in[1];   // c_attn_w [E,3E]
    const float* ba = (const float*)d_in[2];   // c_attn_b [3E]
    const float* wp = (const float*)d_in[3];   // c_proj_w [E,E]
    const float* bp = (const float*)d_in[4];   // c_proj_b [E]
    float* out = (float*)d_out;

    float* qkv = nullptr;
    float* att = nullptr;
    cudaGetSymbolAddress((void**)&qkv, g_qkv);
    cudaGetSymbolAddress((void**)&att, g_attn);

    // 1) QKV projection: [4096,1024] @ [1024,3072] + b
    sgemm_bias<<<dim3((3 * Ec) / 128, M_TOK / 128), 256>>>(
        x, wa, ba, qkv, M_TOK, 3 * Ec, Ec);

    // 2) causal multi-head attention
    attn_kernel<<<dim3(Sc / 128, Hc, Bc), 128>>>(qkv, att);

    // 3) output projection: [4096,1024] @ [1024,1024] + b
    sgemm_bias<<<dim3(Ec / 128, M_TOK / 128), 256>>>(
        att, wp, bp, out, M_TOK, Ec, Ec);
}

// round 2
// speedup vs baseline: 1.4221x; 1.4221x over previous
#include <cuda_runtime.h>
#include <cuda_bf16.h>

// Problem constants
#define Bc 2
#define Sc 2048
#define Ec 1024
#define Hc 16
#define Dc 64
#define M_TOK (Bc * Sc)          // 4096 rows

// Scratch (no cudaMalloc allowed)
__device__ float g_qkv[(size_t)Bc * Sc * 3 * Ec];   // [B,S,3E]
__device__ float g_attn[(size_t)Bc * Sc * Ec];      // [B,S,E]

__device__ __forceinline__ unsigned f2tf32(float x) {
    unsigned r;
    asm("cvt.rna.tf32.f32 %0, %1;" : "=r"(r) : "f"(x));
    return r;
}

__device__ __forceinline__ void mma_tf32(float* d, const unsigned* a, const unsigned* b) {
    asm volatile(
        "mma.sync.aligned.m16n8k8.row.col.f32.tf32.tf32.f32 "
        "{%0,%1,%2,%3}, {%4,%5,%6,%7}, {%8,%9}, {%0,%1,%2,%3};"
        : "+f"(d[0]), "+f"(d[1]), "+f"(d[2]), "+f"(d[3])
        : "r"(a[0]), "r"(a[1]), "r"(a[2]), "r"(a[3]), "r"(b[0]), "r"(b[1]));
}

// ---------------------------------------------------------------------------
// tf32 tensor-core GEMM + bias: C[M,N] = A[M,K] @ B[K,N] + bias[N]
// BM=128, BN=128, BK=32. 256 threads = 8 warps (4m x 2n), warp tile 32x64.
// Double-buffered smem, register staging, 1 sync/iter.
// Smem layouts (conflict-free for both STS and frag LDS):
//   As: [2][128][36]  (A^T-ish: [m][k], stride 36 -> 4m+k bank pattern)
//   Bs: [2][32][136]  ([k][n], stride 136 -> 8k+n bank pattern)
// Requires M%128==0, N%128==0, K%32==0.
// ---------------------------------------------------------------------------
#define AS_STRIDE 36
#define BS_STRIDE 136
#define AS_BUF (128 * AS_STRIDE)   // 4608 words
#define BS_BUF (32 * BS_STRIDE)    // 4352 words
#define GEMM_SMEM_BYTES ((2 * AS_BUF + 2 * BS_BUF) * 4)  // 71680

__global__ __launch_bounds__(256, 2)
void gemm_tf32(const float* __restrict__ A, const float* __restrict__ B,
               const float* __restrict__ bias, float* __restrict__ C,
               int M, int N, int K)
{
    extern __shared__ unsigned sm[];
    unsigned* As = sm;               // [2][128][36]
    unsigned* Bs = sm + 2 * AS_BUF;  // [2][32][136]

    const int tid  = threadIdx.x;
    const int warp = tid >> 5, lane = tid & 31;
    const int g = lane >> 2, t = lane & 3;
    const int wm = (warp >> 1) * 32;     // 0,32,64,96
    const int wn = (warp & 1) * 64;      // 0,64
    const int bm = blockIdx.y * 128;
    const int bn = blockIdx.x * 128;

    // Staging index maps
    const int am  = tid >> 3;            // A row group (0..31), +i*32
    const int ak  = (tid & 7) * 4;       // A k offset (0,4,..,28)
    const int bk  = tid >> 5;            // B k row (0..7), +i*8
    const int bn4 = (tid & 31) * 4;      // B col offset

    float4 ar[4], br[4];
    // prologue: load k-chunk 0
#pragma unroll
    for (int i = 0; i < 4; i++) {
        ar[i] = *(const float4*)&A[(size_t)(bm + am + i * 32) * K + ak];
        br[i] = *(const float4*)&B[(size_t)(bk + i * 8) * N + bn + bn4];
    }

    float acc[2][8][4];
#pragma unroll
    for (int mi = 0; mi < 2; mi++)
#pragma unroll
        for (int ni = 0; ni < 8; ni++)
#pragma unroll
            for (int r = 0; r < 4; r++) acc[mi][ni][r] = 0.f;

    const int iters = K / 32;
    for (int it = 0; it < iters; it++) {
        const int cur = it & 1;
        unsigned* Ac = As + cur * AS_BUF;
        unsigned* Bc2 = Bs + cur * BS_BUF;

        // STS staged regs (convert to tf32)
#pragma unroll
        for (int i = 0; i < 4; i++) {
            uint4 u;
            u.x = f2tf32(ar[i].x); u.y = f2tf32(ar[i].y);
            u.z = f2tf32(ar[i].z); u.w = f2tf32(ar[i].w);
            *(uint4*)&Ac[(am + i * 32) * AS_STRIDE + ak] = u;
            uint4 v;
            v.x = f2tf32(br[i].x); v.y = f2tf32(br[i].y);
            v.z = f2tf32(br[i].z); v.w = f2tf32(br[i].w);
            *(uint4*)&Bc2[(bk + i * 8) * BS_STRIDE + bn4] = v;
        }
        __syncthreads();

        // prefetch next k-chunk while computing this one
        if (it + 1 < iters) {
            const int k0 = (it + 1) * 32;
#pragma unroll
            for (int i = 0; i < 4; i++) {
                ar[i] = *(const float4*)&A[(size_t)(bm + am + i * 32) * K + k0 + ak];
                br[i] = *(const float4*)&B[(size_t)(k0 + bk + i * 8) * N + bn + bn4];
            }
        }

        // 4 k8-steps of MMA
#pragma unroll
        for (int ks = 0; ks < 4; ks++) {
            const int kb = ks * 8;
            unsigned af[2][4];
#pragma unroll
            for (int mi = 0; mi < 2; mi++) {
                const unsigned* p = Ac + (wm + mi * 16) * AS_STRIDE;
                af[mi][0] = p[(g)     * AS_STRIDE + kb + t];
                af[mi][1] = p[(g + 8) * AS_STRIDE + kb + t];
                af[mi][2] = p[(g)     * AS_STRIDE + kb + t + 4];
                af[mi][3] = p[(g + 8) * AS_STRIDE + kb + t + 4];
            }
            unsigned bf[8][2];
#pragma unroll
            for (int ni = 0; ni < 8; ni++) {
                bf[ni][0] = Bc2[(kb + t)     * BS_STRIDE + wn + ni * 8 + g];
                bf[ni][1] = Bc2[(kb + t + 4) * BS_STRIDE + wn + ni * 8 + g];
            }
#pragma unroll
            for (int mi = 0; mi < 2; mi++)
#pragma unroll
                for (int ni = 0; ni < 8; ni++)
                    mma_tf32(acc[mi][ni], af[mi], bf[ni]);
        }
        __syncthreads();
    }

    // epilogue: add bias, store
#pragma unroll
    for (int mi = 0; mi < 2; mi++) {
        const int r0 = bm + wm + mi * 16 + g;
#pragma unroll
        for (int ni = 0; ni < 8; ni++) {
            const int c = bn + wn + ni * 8 + t * 2;
            const float b0 = bias[c], b1 = bias[c + 1];
            float2 o0 = make_float2(acc[mi][ni][0] + b0, acc[mi][ni][1] + b1);
            float2 o1 = make_float2(acc[mi][ni][2] + b0, acc[mi][ni][3] + b1);
            *(float2*)&C[(size_t)r0 * N + c] = o0;
            *(float2*)&C[(size_t)(r0 + 8) * N + c] = o1;
        }
    }
}

// ---------------------------------------------------------------------------
// Flash-style causal attention, fp32 (unchanged from round 1 — profiling target
// for next round).
// ---------------------------------------------------------------------------
__global__ __launch_bounds__(128)
void attn_kernel(const float* __restrict__ qkv, float* __restrict__ out)
{
    const int qt = blockIdx.x;
    const int h  = blockIdx.y;
    const int b  = blockIdx.z;
    const int tid = threadIdx.x;
    const int q_idx = qt * 128 + tid;

    __shared__ float Ks[64][68];
    __shared__ float Vs[64][68];

    float q[Dc];
    {
        const float* qptr = qkv + ((size_t)(b * Sc + q_idx)) * (3 * Ec) + h * Dc;
#pragma unroll
        for (int d = 0; d < Dc; d += 4) {
            float4 v = *(const float4*)(qptr + d);
            q[d] = v.x; q[d + 1] = v.y; q[d + 2] = v.z; q[d + 3] = v.w;
        }
    }

    float accO[Dc];
#pragma unroll
    for (int d = 0; d < Dc; d++) accO[d] = 0.f;
    float m = -1e30f;
    float l = 0.f;

    const int n_tiles = 2 * (qt + 1);
    const float scale = 0.125f;

    float s[64];

    for (int kt = 0; kt < n_tiles; kt++) {
        const int k0 = kt * 64;
        __syncthreads();
        {
            int r = tid & 63;
            const float* src = qkv + ((size_t)(b * Sc + k0 + r)) * (3 * Ec)
                               + ((tid < 64) ? Ec : 2 * Ec) + h * Dc;
            float* dst = (tid < 64) ? &Ks[r][0] : &Vs[r][0];
#pragma unroll
            for (int d = 0; d < Dc; d += 4) {
                *(float4*)(dst + d) = *(const float4*)(src + d);
            }
        }
        __syncthreads();

        const bool need_mask = (k0 + 63 > q_idx);
#pragma unroll 8
        for (int j = 0; j < 64; j++) {
            float sum = 0.f;
#pragma unroll
            for (int d4 = 0; d4 < 16; d4++) {
                float4 kv = *(const float4*)&Ks[j][d4 * 4];
                sum += q[d4 * 4 + 0] * kv.x;
                sum += q[d4 * 4 + 1] * kv.y;
                sum += q[d4 * 4 + 2] * kv.z;
                sum += q[d4 * 4 + 3] * kv.w;
            }
            sum *= scale;
            if (need_mask && (k0 + j > q_idx)) sum = -1e30f;
            s[j] = sum;
        }

        float tmax = -1e30f;
#pragma unroll 16
        for (int j = 0; j < 64; j++) tmax = fmaxf(tmax, s[j]);

        float mnew = fmaxf(m, tmax);
        float corr = __expf(m - mnew);
        l *= corr;
#pragma unroll
        for (int d = 0; d < Dc; d++) accO[d] *= corr;
        m = mnew;

#pragma unroll 8
        for (int j = 0; j < 64; j++) {
            float p = __expf(s[j] - mnew);
            l += p;
#pragma unroll
            for (int d4 = 0; d4 < 16; d4++) {
                float4 vv = *(const float4*)&Vs[j][d4 * 4];
                accO[d4 * 4 + 0] += p * vv.x;
                accO[d4 * 4 + 1] += p * vv.y;
                accO[d4 * 4 + 2] += p * vv.z;
                accO[d4 * 4 + 3] += p * vv.w;
            }
        }
    }

    {
        float inv = 1.f / l;
        float* optr = out + ((size_t)(b * Sc + q_idx)) * Ec + h * Dc;
#pragma unroll
        for (int d = 0; d < Dc; d += 4) {
            float4 o;
            o.x = accO[d + 0] * inv;
            o.y = accO[d + 1] * inv;
            o.z = accO[d + 2] * inv;
            o.w = accO[d + 3] * inv;
            *(float4*)(optr + d) = o;
        }
    }
}

// ---------------------------------------------------------------------------
extern "C" void kernel_launch(void* const* d_in, const int* in_sizes, int n_in,
                              void* d_out, int out_size)
{
    const float* x  = (const float*)d_in[0];   // hidden_states [B,S,E]
    const float* wa = (const float*)d_in[1];   // c_attn_w [E,3E]
    const float* ba = (const float*)d_in[2];   // c_attn_b [3E]
    const float* wp = (const float*)d_in[3];   // c_proj_w [E,E]
    const float* bp = (const float*)d_in[4];   // c_proj_b [E]
    float* out = (float*)d_out;

    float* qkv = nullptr;
    float* att = nullptr;
    cudaGetSymbolAddress((void**)&qkv, g_qkv);
    cudaGetSymbolAddress((void**)&att, g_attn);

    cudaFuncSetAttribute(gemm_tf32, cudaFuncAttributeMaxDynamicSharedMemorySize,
                         GEMM_SMEM_BYTES);

    // 1) QKV projection: [4096,1024] @ [1024,3072] + b
    gemm_tf32<<<dim3((3 * Ec) / 128, M_TOK / 128), 256, GEMM_SMEM_BYTES>>>(
        x, wa, ba, qkv, M_TOK, 3 * Ec, Ec);

    // 2) causal multi-head attention
    attn_kernel<<<dim3(Sc / 128, Hc, Bc), 128>>>(qkv, att);

    // 3) output projection: [4096,1024] @ [1024,1024] + b
    gemm_tf32<<<dim3(Ec / 128, M_TOK / 128), 256, GEMM_SMEM_BYTES>>>(
        att, wp, bp, out, M_TOK, Ec, Ec);
}

// round 3
// speedup vs baseline: 3.4141x; 2.4008x over previous
#include <cuda_runtime.h>
#include <cuda_bf16.h>

// Problem constants
#define Bc 2
#define Sc 2048
#define Ec 1024
#define Hc 16
#define Dc 64
#define M_TOK (Bc * Sc)          // 4096 rows

// Scratch (no cudaMalloc allowed)
__device__ float g_qkv[(size_t)Bc * Sc * 3 * Ec];   // [B,S,3E]
__device__ float g_attn[(size_t)Bc * Sc * Ec];      // [B,S,E]

__device__ __forceinline__ unsigned f2tf32(float x) {
    unsigned r;
    asm("cvt.rna.tf32.f32 %0, %1;" : "=r"(r) : "f"(x));
    return r;
}

__device__ __forceinline__ void mma_tf32(float* d, const unsigned* a, const unsigned* b) {
    asm volatile(
        "mma.sync.aligned.m16n8k8.row.col.f32.tf32.tf32.f32 "
        "{%0,%1,%2,%3}, {%4,%5,%6,%7}, {%8,%9}, {%0,%1,%2,%3};"
        : "+f"(d[0]), "+f"(d[1]), "+f"(d[2]), "+f"(d[3])
        : "r"(a[0]), "r"(a[1]), "r"(a[2]), "r"(a[3]), "r"(b[0]), "r"(b[1]));
}

// ---------------------------------------------------------------------------
// tf32 tensor-core GEMM + bias (unchanged from round 2)
// ---------------------------------------------------------------------------
#define AS_STRIDE 36
#define BS_STRIDE 136
#define AS_BUF (128 * AS_STRIDE)
#define BS_BUF (32 * BS_STRIDE)
#define GEMM_SMEM_BYTES ((2 * AS_BUF + 2 * BS_BUF) * 4)  // 71680

__global__ __launch_bounds__(256, 2)
void gemm_tf32(const float* __restrict__ A, const float* __restrict__ B,
               const float* __restrict__ bias, float* __restrict__ C,
               int M, int N, int K)
{
    extern __shared__ unsigned sm[];
    unsigned* As = sm;
    unsigned* Bs = sm + 2 * AS_BUF;

    const int tid  = threadIdx.x;
    const int warp = tid >> 5, lane = tid & 31;
    const int g = lane >> 2, t = lane & 3;
    const int wm = (warp >> 1) * 32;
    const int wn = (warp & 1) * 64;
    const int bm = blockIdx.y * 128;
    const int bn = blockIdx.x * 128;

    const int am  = tid >> 3;
    const int ak  = (tid & 7) * 4;
    const int bk  = tid >> 5;
    const int bn4 = (tid & 31) * 4;

    float4 ar[4], br[4];
#pragma unroll
    for (int i = 0; i < 4; i++) {
        ar[i] = *(const float4*)&A[(size_t)(bm + am + i * 32) * K + ak];
        br[i] = *(const float4*)&B[(size_t)(bk + i * 8) * N + bn + bn4];
    }

    float acc[2][8][4];
#pragma unroll
    for (int mi = 0; mi < 2; mi++)
#pragma unroll
        for (int ni = 0; ni < 8; ni++)
#pragma unroll
            for (int r = 0; r < 4; r++) acc[mi][ni][r] = 0.f;

    const int iters = K / 32;
    for (int it = 0; it < iters; it++) {
        const int cur = it & 1;
        unsigned* Ac = As + cur * AS_BUF;
        unsigned* Bc2 = Bs + cur * BS_BUF;

#pragma unroll
        for (int i = 0; i < 4; i++) {
            uint4 u;
            u.x = f2tf32(ar[i].x); u.y = f2tf32(ar[i].y);
            u.z = f2tf32(ar[i].z); u.w = f2tf32(ar[i].w);
            *(uint4*)&Ac[(am + i * 32) * AS_STRIDE + ak] = u;
            uint4 v;
            v.x = f2tf32(br[i].x); v.y = f2tf32(br[i].y);
            v.z = f2tf32(br[i].z); v.w = f2tf32(br[i].w);
            *(uint4*)&Bc2[(bk + i * 8) * BS_STRIDE + bn4] = v;
        }
        __syncthreads();

        if (it + 1 < iters) {
            const int k0 = (it + 1) * 32;
#pragma unroll
            for (int i = 0; i < 4; i++) {
                ar[i] = *(const float4*)&A[(size_t)(bm + am + i * 32) * K + k0 + ak];
                br[i] = *(const float4*)&B[(size_t)(k0 + bk + i * 8) * N + bn + bn4];
            }
        }

#pragma unroll
        for (int ks = 0; ks < 4; ks++) {
            const int kb = ks * 8;
            unsigned af[2][4];
#pragma unroll
            for (int mi = 0; mi < 2; mi++) {
                const unsigned* p = Ac + (wm + mi * 16) * AS_STRIDE;
                af[mi][0] = p[(g)     * AS_STRIDE + kb + t];
                af[mi][1] = p[(g + 8) * AS_STRIDE + kb + t];
                af[mi][2] = p[(g)     * AS_STRIDE + kb + t + 4];
                af[mi][3] = p[(g + 8) * AS_STRIDE + kb + t + 4];
            }
            unsigned bf[8][2];
#pragma unroll
            for (int ni = 0; ni < 8; ni++) {
                bf[ni][0] = Bc2[(kb + t)     * BS_STRIDE + wn + ni * 8 + g];
                bf[ni][1] = Bc2[(kb + t + 4) * BS_STRIDE + wn + ni * 8 + g];
            }
#pragma unroll
            for (int mi = 0; mi < 2; mi++)
#pragma unroll
                for (int ni = 0; ni < 8; ni++)
                    mma_tf32(acc[mi][ni], af[mi], bf[ni]);
        }
        __syncthreads();
    }

#pragma unroll
    for (int mi = 0; mi < 2; mi++) {
        const int r0 = bm + wm + mi * 16 + g;
#pragma unroll
        for (int ni = 0; ni < 8; ni++) {
            const int c = bn + wn + ni * 8 + t * 2;
            const float b0 = bias[c], b1 = bias[c + 1];
            float2 o0 = make_float2(acc[mi][ni][0] + b0, acc[mi][ni][1] + b1);
            float2 o1 = make_float2(acc[mi][ni][2] + b0, acc[mi][ni][3] + b1);
            *(float2*)&C[(size_t)r0 * N + c] = o0;
            *(float2*)&C[(size_t)(r0 + 8) * N + c] = o1;
        }
    }
}

// ---------------------------------------------------------------------------
// Tensor-core flash attention (tf32 mma, fp32 softmax).
// Grid: (S/128, H, B) with reversed qx (long blocks first). Block: 256 thr, 8 warps.
// Warp w owns query rows q0 + w*16 .. +15. Key/value tiles of 64 rows.
// Smem (stride 72 words -> conflict-free 8g+t fragment reads):
//   Ks[64][72], Vs[64][72], Ps[128][72] (Ps doubles as Q staging).
// ---------------------------------------------------------------------------
#define ATT_STRIDE 72
#define ATT_KS_OFF 0
#define ATT_VS_OFF (64 * ATT_STRIDE)
#define ATT_PS_OFF (128 * ATT_STRIDE)
#define ATT_SMEM_BYTES ((128 * ATT_STRIDE + 128 * ATT_STRIDE) * 4)  // 73728

__global__ __launch_bounds__(256)
void attn_tc(const float* __restrict__ qkv, float* __restrict__ out)
{
    extern __shared__ unsigned sm[];
    unsigned* Ks = sm + ATT_KS_OFF;
    unsigned* Vs = sm + ATT_VS_OFF;
    unsigned* Ps = sm + ATT_PS_OFF;

    const int qx = (int)gridDim.x - 1 - (int)blockIdx.x;  // long blocks first
    const int h  = blockIdx.y;
    const int b  = blockIdx.z;
    const int tid  = threadIdx.x;
    const int warp = tid >> 5, lane = tid & 31;
    const int g = lane >> 2, t = lane & 3;
    const int q0 = qx * 128;

    const float* base = qkv + (size_t)b * Sc * (3 * Ec) + h * Dc;

    // ---- Stage Q (scaled by 1/8) into Ps, then pull A-frags to registers ----
#pragma unroll
    for (int i = 0; i < 8; i++) {
        int idx = tid + i * 256;            // 0..2047
        int row = idx >> 4;                 // 0..127
        int c4  = (idx & 15) * 4;
        float4 v = *(const float4*)(base + (size_t)(q0 + row) * (3 * Ec) + c4);
        uint4 u;
        u.x = f2tf32(v.x * 0.125f); u.y = f2tf32(v.y * 0.125f);
        u.z = f2tf32(v.z * 0.125f); u.w = f2tf32(v.w * 0.125f);
        *(uint4*)&Ps[row * ATT_STRIDE + c4] = u;
    }
    __syncthreads();

    unsigned qf[8][4];
    {
        const unsigned* p = Ps + (warp * 16) * ATT_STRIDE;
#pragma unroll
        for (int ks = 0; ks < 8; ks++) {
            int kb = ks * 8;
            qf[ks][0] = p[(g)     * ATT_STRIDE + kb + t];
            qf[ks][1] = p[(g + 8) * ATT_STRIDE + kb + t];
            qf[ks][2] = p[(g)     * ATT_STRIDE + kb + t + 4];
            qf[ks][3] = p[(g + 8) * ATT_STRIDE + kb + t + 4];
        }
    }
    __syncthreads();   // Ps now reusable for P tiles

    float o[8][4];
#pragma unroll
    for (int ni = 0; ni < 8; ni++)
#pragma unroll
        for (int r = 0; r < 4; r++) o[ni][r] = 0.f;

    float mA = -1e30f, mB = -1e30f, lA = 0.f, lB = 0.f;
    const int rowA = q0 + warp * 16 + g;
    const int warp_row0 = q0 + warp * 16;

    const int n_tiles = 2 * (qx + 1);
    unsigned* Pw = Ps + (warp * 16) * ATT_STRIDE;  // warp-private P tile

    for (int kt = 0; kt < n_tiles; kt++) {
        const int k0 = kt * 64;

        // ---- load K,V tile (tf32 convert at STS) ----
#pragma unroll
        for (int i = 0; i < 4; i++) {
            int idx = tid + i * 256;        // 0..1023
            int r = idx >> 4;               // 0..63
            int c = (idx & 15) * 4;
            const float* kp = base + (size_t)(k0 + r) * (3 * Ec) + Ec + c;
            float4 kv = *(const float4*)kp;
            float4 vv = *(const float4*)(kp + Ec);
            uint4 uk, uv;
            uk.x = f2tf32(kv.x); uk.y = f2tf32(kv.y);
            uk.z = f2tf32(kv.z); uk.w = f2tf32(kv.w);
            uv.x = f2tf32(vv.x); uv.y = f2tf32(vv.y);
            uv.z = f2tf32(vv.z); uv.w = f2tf32(vv.w);
            *(uint4*)&Ks[r * ATT_STRIDE + c] = uk;
            *(uint4*)&Vs[r * ATT_STRIDE + c] = uv;
        }
        __syncthreads();

        // ---- S = Q K^T (warp tile 16x64) ----
        float sacc[8][4];
#pragma unroll
        for (int ni = 0; ni < 8; ni++)
#pragma unroll
            for (int r = 0; r < 4; r++) sacc[ni][r] = 0.f;

#pragma unroll
        for (int ks = 0; ks < 8; ks++) {
            int kb = ks * 8;
            unsigned bf[8][2];
#pragma unroll
            for (int ni = 0; ni < 8; ni++) {
                bf[ni][0] = Ks[(ni * 8 + g) * ATT_STRIDE + kb + t];
                bf[ni][1] = Ks[(ni * 8 + g) * ATT_STRIDE + kb + t + 4];
            }
#pragma unroll
            for (int ni = 0; ni < 8; ni++)
                mma_tf32(sacc[ni], qf[ks], bf[ni]);
        }

        // ---- causal mask (warp-uniform condition) ----
        if (k0 + 63 > warp_row0) {
#pragma unroll
            for (int ni = 0; ni < 8; ni++) {
                int c0 = k0 + ni * 8 + 2 * t;
                if (c0     > rowA)     sacc[ni][0] = -1e30f;
                if (c0 + 1 > rowA)     sacc[ni][1] = -1e30f;
                if (c0     > rowA + 8) sacc[ni][2] = -1e30f;
                if (c0 + 1 > rowA + 8) sacc[ni][3] = -1e30f;
            }
        }

        // ---- online softmax ----
        float mxA = -1e30f, mxB = -1e30f;
#pragma unroll
        for (int ni = 0; ni < 8; ni++) {
            mxA = fmaxf(mxA, fmaxf(sacc[ni][0], sacc[ni][1]));
            mxB = fmaxf(mxB, fmaxf(sacc[ni][2], sacc[ni][3]));
        }
        mxA = fmaxf(mxA, __shfl_xor_sync(0xffffffffu, mxA, 1));
        mxA = fmaxf(mxA, __shfl_xor_sync(0xffffffffu, mxA, 2));
        mxB = fmaxf(mxB, __shfl_xor_sync(0xffffffffu, mxB, 1));
        mxB = fmaxf(mxB, __shfl_xor_sync(0xffffffffu, mxB, 2));

        float mnA = fmaxf(mA, mxA), mnB = fmaxf(mB, mxB);
        float corrA = __expf(mA - mnA), corrB = __expf(mB - mnB);
        mA = mnA; mB = mnB;

        float sumA = 0.f, sumB = 0.f;
#pragma unroll
        for (int ni = 0; ni < 8; ni++) {
            float p0 = __expf(sacc[ni][0] - mA);
            float p1 = __expf(sacc[ni][1] - mA);
            float p2 = __expf(sacc[ni][2] - mB);
            float p3 = __expf(sacc[ni][3] - mB);
            sacc[ni][0] = p0; sacc[ni][1] = p1;
            sacc[ni][2] = p2; sacc[ni][3] = p3;
            sumA += p0 + p1; sumB += p2 + p3;
        }
        sumA += __shfl_xor_sync(0xffffffffu, sumA, 1);
        sumA += __shfl_xor_sync(0xffffffffu, sumA, 2);
        sumB += __shfl_xor_sync(0xffffffffu, sumB, 1);
        sumB += __shfl_xor_sync(0xffffffffu, sumB, 2);
        lA = lA * corrA + sumA;
        lB = lB * corrB + sumB;

        // rescale O accumulators
#pragma unroll
        for (int ni = 0; ni < 8; ni++) {
            o[ni][0] *= corrA; o[ni][1] *= corrA;
            o[ni][2] *= corrB; o[ni][3] *= corrB;
        }

        // ---- write P (tf32) to warp-private smem, C-layout -> A-layout ----
#pragma unroll
        for (int ni = 0; ni < 8; ni++) {
            uint2 ua, ub;
            ua.x = f2tf32(sacc[ni][0]); ua.y = f2tf32(sacc[ni][1]);
            ub.x = f2tf32(sacc[ni][2]); ub.y = f2tf32(sacc[ni][3]);
            *(uint2*)&Pw[(g)     * ATT_STRIDE + ni * 8 + 2 * t] = ua;
            *(uint2*)&Pw[(g + 8) * ATT_STRIDE + ni * 8 + 2 * t] = ub;
        }
        __syncwarp();

        // ---- O += P V ----
#pragma unroll
        for (int ks = 0; ks < 8; ks++) {
            int kb = ks * 8;
            unsigned pa[4];
            pa[0] = Pw[(g)     * ATT_STRIDE + kb + t];
            pa[1] = Pw[(g + 8) * ATT_STRIDE + kb + t];
            pa[2] = Pw[(g)     * ATT_STRIDE + kb + t + 4];
            pa[3] = Pw[(g + 8) * ATT_STRIDE + kb + t + 4];
            unsigned vb[8][2];
#pragma unroll
            for (int ni = 0; ni < 8; ni++) {
                vb[ni][0] = Vs[(kb + t)     * ATT_STRIDE + ni * 8 + g];
                vb[ni][1] = Vs[(kb + t + 4) * ATT_STRIDE + ni * 8 + g];
            }
#pragma unroll
            for (int ni = 0; ni < 8; ni++)
                mma_tf32(o[ni], pa, vb[ni]);
        }
        __syncthreads();   // protect Ks/Vs before next tile's load
    }

    // ---- epilogue: normalize and store [B,S,E] ----
    const float invA = 1.f / lA, invB = 1.f / lB;
    float* orow = out + (size_t)(b * Sc + rowA) * Ec + h * Dc;
#pragma unroll
    for (int ni = 0; ni < 8; ni++) {
        int c = ni * 8 + 2 * t;
        float2 oa = make_float2(o[ni][0] * invA, o[ni][1] * invA);
        float2 ob = make_float2(o[ni][2] * invB, o[ni][3] * invB);
        *(float2*)(orow + c) = oa;
        *(float2*)(orow + (size_t)8 * Ec + c) = ob;
    }
}

// ---------------------------------------------------------------------------
extern "C" void kernel_launch(void* const* d_in, const int* in_sizes, int n_in,
                              void* d_out, int out_size)
{
    const float* x  = (const float*)d_in[0];   // hidden_states [B,S,E]
    const float* wa = (const float*)d_in[1];   // c_attn_w [E,3E]
    const float* ba = (const float*)d_in[2];   // c_attn_b [3E]
    const float* wp = (const float*)d_in[3];   // c_proj_w [E,E]
    const float* bp = (const float*)d_in[4];   // c_proj_b [E]
    float* out = (float*)d_out;

    float* qkv = nullptr;
    float* att = nullptr;
    cudaGetSymbolAddress((void**)&qkv, g_qkv);
    cudaGetSymbolAddress((void**)&att, g_attn);

    cudaFuncSetAttribute(gemm_tf32, cudaFuncAttributeMaxDynamicSharedMemorySize,
                         GEMM_SMEM_BYTES);
    cudaFuncSetAttribute(attn_tc, cudaFuncAttributeMaxDynamicSharedMemorySize,
                         ATT_SMEM_BYTES);

    // 1) QKV projection
    gemm_tf32<<<dim3((3 * Ec) / 128, M_TOK / 128), 256, GEMM_SMEM_BYTES>>>(
        x, wa, ba, qkv, M_TOK, 3 * Ec, Ec);

    // 2) tensor-core causal attention
    attn_tc<<<dim3(Sc / 128, Hc, Bc), 256, ATT_SMEM_BYTES>>>(qkv, att);

    // 3) output projection
    gemm_tf32<<<dim3(Ec / 128, M_TOK / 128), 256, GEMM_SMEM_BYTES>>>(
        att, wp, bp, out, M_TOK, Ec, Ec);
}

// round 4
// speedup vs baseline: 3.6764x; 1.0768x over previous
#include <cuda_runtime.h>
#include <cuda_bf16.h>

// Problem constants
#define Bc 2
#define Sc 2048
#define Ec 1024
#define Hc 16
#define Dc 64
#define M_TOK (Bc * Sc)          // 4096 rows

// Scratch (tf32 bit patterns stored as unsigned)
__device__ unsigned g_xc [(size_t)M_TOK * Ec];        // hidden_states (tf32)
__device__ unsigned g_wac[(size_t)Ec * 3 * Ec];       // c_attn_w (tf32)
__device__ unsigned g_wpc[(size_t)Ec * Ec];           // c_proj_w (tf32)
__device__ unsigned g_qkv[(size_t)M_TOK * 3 * Ec];    // qkv (tf32)
__device__ unsigned g_att[(size_t)M_TOK * Ec];        // attn out (tf32)

__device__ __forceinline__ unsigned f2tf32(float x) {
    unsigned r;
    asm("cvt.rna.tf32.f32 %0, %1;" : "=r"(r) : "f"(x));
    return r;
}

__device__ __forceinline__ void mma_tf32(float* d, const unsigned* a, const unsigned* b) {
    asm volatile(
        "mma.sync.aligned.m16n8k8.row.col.f32.tf32.tf32.f32 "
        "{%0,%1,%2,%3}, {%4,%5,%6,%7}, {%8,%9}, {%0,%1,%2,%3};"
        : "+f"(d[0]), "+f"(d[1]), "+f"(d[2]), "+f"(d[3])
        : "r"(a[0]), "r"(a[1]), "r"(a[2]), "r"(a[3]), "r"(b[0]), "r"(b[1]));
}

__device__ __forceinline__ void cp_async16(unsigned* dst_smem, const unsigned* src) {
    unsigned d = (unsigned)__cvta_generic_to_shared(dst_smem);
    asm volatile("cp.async.cg.shared.global [%0], [%1], 16;\n" :: "r"(d), "l"(src));
}
#define CP_COMMIT() asm volatile("cp.async.commit_group;\n" ::: "memory")
#define CP_WAIT0()  asm volatile("cp.async.wait_group 0;\n" ::: "memory")

// ---------------------------------------------------------------------------
// fp32 -> tf32 bit convert (vectorized)
// ---------------------------------------------------------------------------
__global__ __launch_bounds__(256)
void cvt_tf32_kernel(const float4* __restrict__ s, uint4* __restrict__ d, int n4)
{
    int i = blockIdx.x * blockDim.x + threadIdx.x;
    if (i < n4) {
        float4 v = s[i];
        uint4 u;
        u.x = f2tf32(v.x); u.y = f2tf32(v.y);
        u.z = f2tf32(v.z); u.w = f2tf32(v.w);
        d[i] = u;
    }
}

// ---------------------------------------------------------------------------
// tf32 tensor-core GEMM + bias, pre-converted inputs, cp.async, 1 sync/iter.
// C[M,N] = A[M,K] @ B[K,N] + bias[N].  BM=BN=128, BK=32, 256 thr, warp 32x64.
// OUT_TF32: store tf32 bits (for qkv); else fp32.
// ---------------------------------------------------------------------------
#define AS_STRIDE 36
#define BS_STRIDE 136
#define AS_BUF (128 * AS_STRIDE)
#define BS_BUF (32 * BS_STRIDE)
#define GEMM_SMEM_BYTES ((2 * AS_BUF + 2 * BS_BUF) * 4)  // 71680

template<bool OUT_TF32>
__global__ __launch_bounds__(256, 2)
void gemm_tc(const unsigned* __restrict__ A, const unsigned* __restrict__ B,
             const float* __restrict__ bias, void* __restrict__ Cv,
             int M, int N, int K)
{
    extern __shared__ unsigned sm[];
    unsigned* As = sm;               // [2][128][36]
    unsigned* Bs = sm + 2 * AS_BUF;  // [2][32][136]

    const int tid  = threadIdx.x;
    const int warp = tid >> 5, lane = tid & 31;
    const int g = lane >> 2, t = lane & 3;
    const int wm = (warp >> 1) * 32;
    const int wn = (warp & 1) * 64;
    const int bm = blockIdx.y * 128;
    const int bn = blockIdx.x * 128;

    const int am  = tid >> 3;
    const int ak  = (tid & 7) * 4;
    const int bk  = tid >> 5;
    const int bn4 = (tid & 31) * 4;

    // issue one k-chunk's copies into buffer buf
    auto issue_tile = [&](int k0, int buf) {
        unsigned* Ad = As + buf * AS_BUF;
        unsigned* Bd = Bs + buf * BS_BUF;
#pragma unroll
        for (int i = 0; i < 4; i++) {
            cp_async16(&Ad[(am + i * 32) * AS_STRIDE + ak],
                       &A[(size_t)(bm + am + i * 32) * K + k0 + ak]);
            cp_async16(&Bd[(bk + i * 8) * BS_STRIDE + bn4],
                       &B[(size_t)(k0 + bk + i * 8) * N + bn + bn4]);
        }
        CP_COMMIT();
    };

    issue_tile(0, 0);

    float acc[2][8][4];
#pragma unroll
    for (int mi = 0; mi < 2; mi++)
#pragma unroll
        for (int ni = 0; ni < 8; ni++)
#pragma unroll
            for (int r = 0; r < 4; r++) acc[mi][ni][r] = 0.f;

    const int iters = K / 32;
    for (int it = 0; it < iters; it++) {
        CP_WAIT0();
        __syncthreads();
        if (it + 1 < iters) issue_tile((it + 1) * 32, (it + 1) & 1);

        const unsigned* Ac = As + (it & 1) * AS_BUF;
        const unsigned* Bc2 = Bs + (it & 1) * BS_BUF;

#pragma unroll
        for (int ks = 0; ks < 4; ks++) {
            const int kb = ks * 8;
            unsigned af[2][4];
#pragma unroll
            for (int mi = 0; mi < 2; mi++) {
                const unsigned* p = Ac + (wm + mi * 16) * AS_STRIDE;
                af[mi][0] = p[(g)     * AS_STRIDE + kb + t];
                af[mi][1] = p[(g + 8) * AS_STRIDE + kb + t];
                af[mi][2] = p[(g)     * AS_STRIDE + kb + t + 4];
                af[mi][3] = p[(g + 8) * AS_STRIDE + kb + t + 4];
            }
            unsigned bf[8][2];
#pragma unroll
            for (int ni = 0; ni < 8; ni++) {
                bf[ni][0] = Bc2[(kb + t)     * BS_STRIDE + wn + ni * 8 + g];
                bf[ni][1] = Bc2[(kb + t + 4) * BS_STRIDE + wn + ni * 8 + g];
            }
#pragma unroll
            for (int mi = 0; mi < 2; mi++)
#pragma unroll
                for (int ni = 0; ni < 8; ni++)
                    mma_tf32(acc[mi][ni], af[mi], bf[ni]);
        }
        // no trailing sync: next iter's copies go to the other buffer, and the
        // top-of-loop barrier orders them after all readers of that buffer.
    }

#pragma unroll
    for (int mi = 0; mi < 2; mi++) {
        const int r0 = bm + wm + mi * 16 + g;
#pragma unroll
        for (int ni = 0; ni < 8; ni++) {
            const int c = bn + wn + ni * 8 + t * 2;
            const float b0 = bias[c], b1 = bias[c + 1];
            if (OUT_TF32) {
                unsigned* C = (unsigned*)Cv;
                uint2 o0 = make_uint2(f2tf32(acc[mi][ni][0] + b0), f2tf32(acc[mi][ni][1] + b1));
                uint2 o1 = make_uint2(f2tf32(acc[mi][ni][2] + b0), f2tf32(acc[mi][ni][3] + b1));
                *(uint2*)&C[(size_t)r0 * N + c] = o0;
                *(uint2*)&C[(size_t)(r0 + 8) * N + c] = o1;
            } else {
                float* C = (float*)Cv;
                float2 o0 = make_float2(acc[mi][ni][0] + b0, acc[mi][ni][1] + b1);
                float2 o1 = make_float2(acc[mi][ni][2] + b0, acc[mi][ni][3] + b1);
                *(float2*)&C[(size_t)r0 * N + c] = o0;
                *(float2*)&C[(size_t)(r0 + 8) * N + c] = o1;
            }
        }
    }
}

// ---------------------------------------------------------------------------
// Tensor-core flash attention, tf32-bit inputs, double-buffered K/V via
// cp.async, 1 syncthreads per tile. Output written as tf32 bits.
// Grid: (S/128, H, B), reversed qx. 256 thr, warp owns 16 query rows.
// Smem words: Ks[2][64][72], Vs[2][64][72], Ps[128][72]  -> 110592 B.
// ---------------------------------------------------------------------------
#define AT_STR 72
#define AT_KBUF (64 * AT_STR)
#define AT_VS_OFF (2 * AT_KBUF)
#define AT_PS_OFF (4 * AT_KBUF)
#define ATT_SMEM_BYTES ((4 * AT_KBUF + 128 * AT_STR) * 4)  // 110592

__global__ __launch_bounds__(256, 2)
void attn_tc(const unsigned* __restrict__ qkv, unsigned* __restrict__ out)
{
    extern __shared__ unsigned sm[];
    unsigned* KsB = sm;
    unsigned* VsB = sm + AT_VS_OFF;
    unsigned* Ps  = sm + AT_PS_OFF;

    const int qx = (int)gridDim.x - 1 - (int)blockIdx.x;  // long blocks first
    const int h  = blockIdx.y;
    const int b  = blockIdx.z;
    const int tid  = threadIdx.x;
    const int warp = tid >> 5, lane = tid & 31;
    const int g = lane >> 2, t = lane & 3;
    const int q0 = qx * 128;

    const unsigned* base = qkv + (size_t)b * Sc * (3 * Ec) + h * Dc;
    const int n_tiles = 2 * (qx + 1);

    auto issue_kv = [&](int k0, int buf) {
        unsigned* Kd = KsB + buf * AT_KBUF;
        unsigned* Vd = VsB + buf * AT_KBUF;
#pragma unroll
        for (int i = 0; i < 4; i++) {
            int idx = tid + i * 256;
            int r = idx >> 4, c = (idx & 15) * 4;
            const unsigned* kp = base + (size_t)(k0 + r) * (3 * Ec) + Ec + c;
            cp_async16(&Kd[r * AT_STR + c], kp);
            cp_async16(&Vd[r * AT_STR + c], kp + Ec);
        }
        CP_COMMIT();
    };

    issue_kv(0, 0);   // overlap tile0 copy with Q staging

    // stage Q (raw tf32 bits) into Ps, pull A-frags
#pragma unroll
    for (int i = 0; i < 8; i++) {
        int idx = tid + i * 256;
        int row = idx >> 4;
        int c4  = (idx & 15) * 4;
        *(uint4*)&Ps[row * AT_STR + c4] =
            *(const uint4*)(base + (size_t)(q0 + row) * (3 * Ec) + c4);
    }
    __syncthreads();

    unsigned qf[8][4];
    {
        const unsigned* p = Ps + (warp * 16) * AT_STR;
#pragma unroll
        for (int ks = 0; ks < 8; ks++) {
            int kb = ks * 8;
            qf[ks][0] = p[(g)     * AT_STR + kb + t];
            qf[ks][1] = p[(g + 8) * AT_STR + kb + t];
            qf[ks][2] = p[(g)     * AT_STR + kb + t + 4];
            qf[ks][3] = p[(g + 8) * AT_STR + kb + t + 4];
        }
    }
    __syncthreads();   // Ps now reusable for P tiles

    float o[8][4];
#pragma unroll
    for (int ni = 0; ni < 8; ni++)
#pragma unroll
        for (int r = 0; r < 4; r++) o[ni][r] = 0.f;

    float mA = -1e30f, mB = -1e30f, lA = 0.f, lB = 0.f;
    const int rowA = q0 + warp * 16 + g;
    const int warp_row0 = q0 + warp * 16;
    unsigned* Pw = Ps + (warp * 16) * AT_STR;

    for (int kt = 0; kt < n_tiles; kt++) {
        const int k0 = kt * 64;
        CP_WAIT0();
        __syncthreads();
        if (kt + 1 < n_tiles) issue_kv((kt + 1) * 64, (kt + 1) & 1);

        const unsigned* Ks = KsB + (kt & 1) * AT_KBUF;
        const unsigned* Vs = VsB + (kt & 1) * AT_KBUF;

        // ---- S = Q K^T ----
        float sacc[8][4];
#pragma unroll
        for (int ni = 0; ni < 8; ni++)
#pragma unroll
            for (int r = 0; r < 4; r++) sacc[ni][r] = 0.f;

#pragma unroll
        for (int ks = 0; ks < 8; ks++) {
            int kb = ks * 8;
            unsigned bf[8][2];
#pragma unroll
            for (int ni = 0; ni < 8; ni++) {
                bf[ni][0] = Ks[(ni * 8 + g) * AT_STR + kb + t];
                bf[ni][1] = Ks[(ni * 8 + g) * AT_STR + kb + t + 4];
            }
#pragma unroll
            for (int ni = 0; ni < 8; ni++)
                mma_tf32(sacc[ni], qf[ks], bf[ni]);
        }

        // ---- scale by 1/sqrt(D) ----
#pragma unroll
        for (int ni = 0; ni < 8; ni++)
#pragma unroll
            for (int r = 0; r < 4; r++) sacc[ni][r] *= 0.125f;

        // ---- causal mask (warp-uniform outer condition) ----
        if (k0 + 63 > warp_row0) {
#pragma unroll
            for (int ni = 0; ni < 8; ni++) {
                int c0 = k0 + ni * 8 + 2 * t;
                if (c0     > rowA)     sacc[ni][0] = -1e30f;
                if (c0 + 1 > rowA)     sacc[ni][1] = -1e30f;
                if (c0     > rowA + 8) sacc[ni][2] = -1e30f;
                if (c0 + 1 > rowA + 8) sacc[ni][3] = -1e30f;
            }
        }

        // ---- online softmax ----
        float mxA = -1e30f, mxB = -1e30f;
#pragma unroll
        for (int ni = 0; ni < 8; ni++) {
            mxA = fmaxf(mxA, fmaxf(sacc[ni][0], sacc[ni][1]));
            mxB = fmaxf(mxB, fmaxf(sacc[ni][2], sacc[ni][3]));
        }
        mxA = fmaxf(mxA, __shfl_xor_sync(0xffffffffu, mxA, 1));
        mxA = fmaxf(mxA, __shfl_xor_sync(0xffffffffu, mxA, 2));
        mxB = fmaxf(mxB, __shfl_xor_sync(0xffffffffu, mxB, 1));
        mxB = fmaxf(mxB, __shfl_xor_sync(0xffffffffu, mxB, 2));

        float mnA = fmaxf(mA, mxA), mnB = fmaxf(mB, mxB);
        float corrA = __expf(mA - mnA), corrB = __expf(mB - mnB);
        mA = mnA; mB = mnB;

        float sumA = 0.f, sumB = 0.f;
#pragma unroll
        for (int ni = 0; ni < 8; ni++) {
            float p0 = __expf(sacc[ni][0] - mA);
            float p1 = __expf(sacc[ni][1] - mA);
            float p2 = __expf(sacc[ni][2] - mB);
            float p3 = __expf(sacc[ni][3] - mB);
            sacc[ni][0] = p0; sacc[ni][1] = p1;
            sacc[ni][2] = p2; sacc[ni][3] = p3;
            sumA += p0 + p1; sumB += p2 + p3;
        }
        sumA += __shfl_xor_sync(0xffffffffu, sumA, 1);
        sumA += __shfl_xor_sync(0xffffffffu, sumA, 2);
        sumB += __shfl_xor_sync(0xffffffffu, sumB, 1);
        sumB += __shfl_xor_sync(0xffffffffu, sumB, 2);
        lA = lA * corrA + sumA;
        lB = lB * corrB + sumB;

#pragma unroll
        for (int ni = 0; ni < 8; ni++) {
            o[ni][0] *= corrA; o[ni][1] *= corrA;
            o[ni][2] *= corrB; o[ni][3] *= corrB;
        }

        // ---- P (tf32) -> warp-private smem: C-layout to A-layout ----
#pragma unroll
        for (int ni = 0; ni < 8; ni++) {
            uint2 ua, ub;
            ua.x = f2tf32(sacc[ni][0]); ua.y = f2tf32(sacc[ni][1]);
            ub.x = f2tf32(sacc[ni][2]); ub.y = f2tf32(sacc[ni][3]);
            *(uint2*)&Pw[(g)     * AT_STR + ni * 8 + 2 * t] = ua;
            *(uint2*)&Pw[(g + 8) * AT_STR + ni * 8 + 2 * t] = ub;
        }
        __syncwarp();

        // ---- O += P V ----
#pragma unroll
        for (int ks = 0; ks < 8; ks++) {
            int kb = ks * 8;
            unsigned pa[4];
            pa[0] = Pw[(g)     * AT_STR + kb + t];
            pa[1] = Pw[(g + 8) * AT_STR + kb + t];
            pa[2] = Pw[(g)     * AT_STR + kb + t + 4];
            pa[3] = Pw[(g + 8) * AT_STR + kb + t + 4];
            unsigned vb[8][2];
#pragma unroll
            for (int ni = 0; ni < 8; ni++) {
                vb[ni][0] = Vs[(kb + t)     * AT_STR + ni * 8 + g];
                vb[ni][1] = Vs[(kb + t + 4) * AT_STR + ni * 8 + g];
            }
#pragma unroll
            for (int ni = 0; ni < 8; ni++)
                mma_tf32(o[ni], pa, vb[ni]);
        }
        // no trailing sync: next tile goes to the other K/V buffer; the
        // top-of-loop barrier orders its copies after this buffer's readers.
        // Pw reuse is ordered by the same barrier.
    }

    // ---- epilogue: normalize, store tf32 bits [B,S,E] ----
    const float invA = 1.f / lA, invB = 1.f / lB;
    unsigned* orow = out + (size_t)(b * Sc + rowA) * Ec + h * Dc;
#pragma unroll
    for (int ni = 0; ni < 8; ni++) {
        int c = ni * 8 + 2 * t;
        uint2 oa = make_uint2(f2tf32(o[ni][0] * invA), f2tf32(o[ni][1] * invA));
        uint2 ob = make_uint2(f2tf32(o[ni][2] * invB), f2tf32(o[ni][3] * invB));
        *(uint2*)(orow + c) = oa;
        *(uint2*)(orow + (size_t)8 * Ec + c) = ob;
    }
}

// ---------------------------------------------------------------------------
extern "C" void kernel_launch(void* const* d_in, const int* in_sizes, int n_in,
                              void* d_out, int out_size)
{
    const float* x  = (const float*)d_in[0];   // hidden_states [B,S,E]
    const float* wa = (const float*)d_in[1];   // c_attn_w [E,3E]
    const float* ba = (const float*)d_in[2];   // c_attn_b [3E]
    const float* wp = (const float*)d_in[3];   // c_proj_w [E,E]
    const float* bp = (const float*)d_in[4];   // c_proj_b [E]
    float* out = (float*)d_out;

    unsigned *xc, *wac, *wpc, *qkv, *att;
    cudaGetSymbolAddress((void**)&xc,  g_xc);
    cudaGetSymbolAddress((void**)&wac, g_wac);
    cudaGetSymbolAddress((void**)&wpc, g_wpc);
    cudaGetSymbolAddress((void**)&qkv, g_qkv);
    cudaGetSymbolAddress((void**)&att, g_att);

    cudaFuncSetAttribute(gemm_tc<true>,  cudaFuncAttributeMaxDynamicSharedMemorySize, GEMM_SMEM_BYTES);
    cudaFuncSetAttribute(gemm_tc<false>, cudaFuncAttributeMaxDynamicSharedMemorySize, GEMM_SMEM_BYTES);
    cudaFuncSetAttribute(attn_tc, cudaFuncAttributeMaxDynamicSharedMemorySize, ATT_SMEM_BYTES);

    // 0) pre-convert inputs to tf32 bits
    {
        int n4x = (M_TOK * Ec) / 4;            // 1048576
        int n4a = (Ec * 3 * Ec) / 4;           // 786432
        int n4p = (Ec * Ec) / 4;               // 262144
        cvt_tf32_kernel<<<n4x / 256, 256>>>((const float4*)x,  (uint4*)xc,  n4x);
        cvt_tf32_kernel<<<n4a / 256, 256>>>((const float4*)wa, (uint4*)wac, n4a);
        cvt_tf32_kernel<<<n4p / 256, 256>>>((const float4*)wp, (uint4*)wpc, n4p);
    }

    // 1) QKV projection -> tf32 bits
    gemm_tc<true><<<dim3((3 * Ec) / 128, M_TOK / 128), 256, GEMM_SMEM_BYTES>>>(
        xc, wac, ba, qkv, M_TOK, 3 * Ec, Ec);

    // 2) tensor-core causal attention -> tf32 bits
    attn_tc<<<dim3(Sc / 128, Hc, Bc), 256, ATT_SMEM_BYTES>>>(qkv, att);

    // 3) output projection -> fp32
    gemm_tc<false><<<dim3(Ec / 128, M_TOK / 128), 256, GEMM_SMEM_BYTES>>>(
        att, wpc, bp, out, M_TOK, Ec, Ec);
}

// round 5
// speedup vs baseline: 4.0303x; 1.0963x over previous
#include <cuda_runtime.h>
#include <cuda_bf16.h>

// Problem constants
#define Bc 2
#define Sc 2048
#define Ec 1024
#define Hc 16
#define Dc 64
#define M_TOK (Bc * Sc)          // 4096 rows

// Scratch (tf32 bit patterns stored as unsigned)
__device__ unsigned g_xc [(size_t)M_TOK * Ec];        // hidden_states (tf32)
__device__ unsigned g_wac[(size_t)Ec * 3 * Ec];       // c_attn_w (tf32)
__device__ unsigned g_wpc[(size_t)Ec * Ec];           // c_proj_w (tf32)
__device__ unsigned g_qkv[(size_t)M_TOK * 3 * Ec];    // qkv (tf32)
__device__ unsigned g_att[(size_t)M_TOK * Ec];        // attn out (tf32)

__device__ __forceinline__ unsigned f2tf32(float x) {
    unsigned r;
    asm("cvt.rna.tf32.f32 %0, %1;" : "=r"(r) : "f"(x));
    return r;
}

__device__ __forceinline__ void mma_tf32(float* d, const unsigned* a, const unsigned* b) {
    asm volatile(
        "mma.sync.aligned.m16n8k8.row.col.f32.tf32.tf32.f32 "
        "{%0,%1,%2,%3}, {%4,%5,%6,%7}, {%8,%9}, {%0,%1,%2,%3};"
        : "+f"(d[0]), "+f"(d[1]), "+f"(d[2]), "+f"(d[3])
        : "r"(a[0]), "r"(a[1]), "r"(a[2]), "r"(a[3]), "r"(b[0]), "r"(b[1]));
}

__device__ __forceinline__ void cp_async16(unsigned* dst_smem, const unsigned* src) {
    unsigned d = (unsigned)__cvta_generic_to_shared(dst_smem);
    asm volatile("cp.async.cg.shared.global [%0], [%1], 16;\n" :: "r"(d), "l"(src));
}
#define CP_COMMIT() asm volatile("cp.async.commit_group;\n" ::: "memory")
#define CP_WAIT0()  asm volatile("cp.async.wait_group 0;\n" ::: "memory")

// ---------------------------------------------------------------------------
// fp32 -> tf32 bit convert (vectorized)
// ---------------------------------------------------------------------------
__global__ __launch_bounds__(256)
void cvt_tf32_kernel(const float4* __restrict__ s, uint4* __restrict__ d, int n4)
{
    int i = blockIdx.x * blockDim.x + threadIdx.x;
    if (i < n4) {
        float4 v = s[i];
        uint4 u;
        u.x = f2tf32(v.x); u.y = f2tf32(v.y);
        u.z = f2tf32(v.z); u.w = f2tf32(v.w);
        d[i] = u;
    }
}

// ---------------------------------------------------------------------------
// tf32 tensor-core GEMM + bias (unchanged from round 4)
// ---------------------------------------------------------------------------
#define AS_STRIDE 36
#define BS_STRIDE 136
#define AS_BUF (128 * AS_STRIDE)
#define BS_BUF (32 * BS_STRIDE)
#define GEMM_SMEM_BYTES ((2 * AS_BUF + 2 * BS_BUF) * 4)  // 71680

template<bool OUT_TF32>
__global__ __launch_bounds__(256, 2)
void gemm_tc(const unsigned* __restrict__ A, const unsigned* __restrict__ B,
             const float* __restrict__ bias, void* __restrict__ Cv,
             int M, int N, int K)
{
    extern __shared__ unsigned sm[];
    unsigned* As = sm;               // [2][128][36]
    unsigned* Bs = sm + 2 * AS_BUF;  // [2][32][136]

    const int tid  = threadIdx.x;
    const int warp = tid >> 5, lane = tid & 31;
    const int g = lane >> 2, t = lane & 3;
    const int wm = (warp >> 1) * 32;
    const int wn = (warp & 1) * 64;
    const int bm = blockIdx.y * 128;
    const int bn = blockIdx.x * 128;

    const int am  = tid >> 3;
    const int ak  = (tid & 7) * 4;
    const int bk  = tid >> 5;
    const int bn4 = (tid & 31) * 4;

    auto issue_tile = [&](int k0, int buf) {
        unsigned* Ad = As + buf * AS_BUF;
        unsigned* Bd = Bs + buf * BS_BUF;
#pragma unroll
        for (int i = 0; i < 4; i++) {
            cp_async16(&Ad[(am + i * 32) * AS_STRIDE + ak],
                       &A[(size_t)(bm + am + i * 32) * K + k0 + ak]);
            cp_async16(&Bd[(bk + i * 8) * BS_STRIDE + bn4],
                       &B[(size_t)(k0 + bk + i * 8) * N + bn + bn4]);
        }
        CP_COMMIT();
    };

    issue_tile(0, 0);

    float acc[2][8][4];
#pragma unroll
    for (int mi = 0; mi < 2; mi++)
#pragma unroll
        for (int ni = 0; ni < 8; ni++)
#pragma unroll
            for (int r = 0; r < 4; r++) acc[mi][ni][r] = 0.f;

    const int iters = K / 32;
    for (int it = 0; it < iters; it++) {
        CP_WAIT0();
        __syncthreads();
        if (it + 1 < iters) issue_tile((it + 1) * 32, (it + 1) & 1);

        const unsigned* Ac = As + (it & 1) * AS_BUF;
        const unsigned* Bc2 = Bs + (it & 1) * BS_BUF;

#pragma unroll
        for (int ks = 0; ks < 4; ks++) {
            const int kb = ks * 8;
            unsigned af[2][4];
#pragma unroll
            for (int mi = 0; mi < 2; mi++) {
                const unsigned* p = Ac + (wm + mi * 16) * AS_STRIDE;
                af[mi][0] = p[(g)     * AS_STRIDE + kb + t];
                af[mi][1] = p[(g + 8) * AS_STRIDE + kb + t];
                af[mi][2] = p[(g)     * AS_STRIDE + kb + t + 4];
                af[mi][3] = p[(g + 8) * AS_STRIDE + kb + t + 4];
            }
            unsigned bf[8][2];
#pragma unroll
            for (int ni = 0; ni < 8; ni++) {
                bf[ni][0] = Bc2[(kb + t)     * BS_STRIDE + wn + ni * 8 + g];
                bf[ni][1] = Bc2[(kb + t + 4) * BS_STRIDE + wn + ni * 8 + g];
            }
#pragma unroll
            for (int mi = 0; mi < 2; mi++)
#pragma unroll
                for (int ni = 0; ni < 8; ni++)
                    mma_tf32(acc[mi][ni], af[mi], bf[ni]);
        }
    }

#pragma unroll
    for (int mi = 0; mi < 2; mi++) {
        const int r0 = bm + wm + mi * 16 + g;
#pragma unroll
        for (int ni = 0; ni < 8; ni++) {
            const int c = bn + wn + ni * 8 + t * 2;
            const float b0 = bias[c], b1 = bias[c + 1];
            if (OUT_TF32) {
                unsigned* C = (unsigned*)Cv;
                uint2 o0 = make_uint2(f2tf32(acc[mi][ni][0] + b0), f2tf32(acc[mi][ni][1] + b1));
                uint2 o1 = make_uint2(f2tf32(acc[mi][ni][2] + b0), f2tf32(acc[mi][ni][3] + b1));
                *(uint2*)&C[(size_t)r0 * N + c] = o0;
                *(uint2*)&C[(size_t)(r0 + 8) * N + c] = o1;
            } else {
                float* C = (float*)Cv;
                float2 o0 = make_float2(acc[mi][ni][0] + b0, acc[mi][ni][1] + b1);
                float2 o1 = make_float2(acc[mi][ni][2] + b0, acc[mi][ni][3] + b1);
                *(float2*)&C[(size_t)r0 * N + c] = o0;
                *(float2*)&C[(size_t)(r0 + 8) * N + c] = o1;
            }
        }
    }
}

// ---------------------------------------------------------------------------
// Tensor-core flash attention, PAIRED query blocks for perfect balance.
// Grid: (S/256, H, B) = (8,16,2) = 256 CTAs -> exactly one wave, each CTA
// processes qx = 15-bx then qx = bx: 34 key-tiles for every CTA.
// 256 thr, warp owns 16 query rows. Double-buffered K/V via cp.async.
// Smem words: Ks[2][64][72], Vs[2][64][72], Ps[128][72]  -> 110592 B.
// ---------------------------------------------------------------------------
#define AT_STR 72
#define AT_KBUF (64 * AT_STR)
#define AT_VS_OFF (2 * AT_KBUF)
#define AT_PS_OFF (4 * AT_KBUF)
#define ATT_SMEM_BYTES ((4 * AT_KBUF + 128 * AT_STR) * 4)  // 110592

__global__ __launch_bounds__(256, 2)
void attn_tc(const unsigned* __restrict__ qkv, unsigned* __restrict__ out)
{
    extern __shared__ unsigned sm[];
    unsigned* KsB = sm;
    unsigned* VsB = sm + AT_VS_OFF;
    unsigned* Ps  = sm + AT_PS_OFF;

    const int h  = blockIdx.y;
    const int b  = blockIdx.z;
    const int tid  = threadIdx.x;
    const int warp = tid >> 5, lane = tid & 31;
    const int g = lane >> 2, t = lane & 3;
    const int nqx = Sc / 128;                      // 16

    const unsigned* base = qkv + (size_t)b * Sc * (3 * Ec) + h * Dc;

    auto issue_kv = [&](int k0, int buf) {
        unsigned* Kd = KsB + buf * AT_KBUF;
        unsigned* Vd = VsB + buf * AT_KBUF;
#pragma unroll
        for (int i = 0; i < 4; i++) {
            int idx = tid + i * 256;
            int r = idx >> 4, c = (idx & 15) * 4;
            const unsigned* kp = base + (size_t)(k0 + r) * (3 * Ec) + Ec + c;
            cp_async16(&Kd[r * AT_STR + c], kp);
            cp_async16(&Vd[r * AT_STR + c], kp + Ec);
        }
        CP_COMMIT();
    };

    for (int pass = 0; pass < 2; pass++) {
        const int qx = pass ? (int)blockIdx.x : (nqx - 1 - (int)blockIdx.x);
        const int q0 = qx * 128;
        const int n_tiles = 2 * (qx + 1);

        // barrier: previous pass's smem readers done before we overwrite
        __syncthreads();
        issue_kv(0, 0);

        // stage Q (raw tf32 bits) into Ps, pull A-frags
#pragma unroll
        for (int i = 0; i < 8; i++) {
            int idx = tid + i * 256;
            int row = idx >> 4;
            int c4  = (idx & 15) * 4;
            *(uint4*)&Ps[row * AT_STR + c4] =
                *(const uint4*)(base + (size_t)(q0 + row) * (3 * Ec) + c4);
        }
        __syncthreads();

        unsigned qf[8][4];
        {
            const unsigned* p = Ps + (warp * 16) * AT_STR;
#pragma unroll
            for (int ks = 0; ks < 8; ks++) {
                int kb = ks * 8;
                qf[ks][0] = p[(g)     * AT_STR + kb + t];
                qf[ks][1] = p[(g + 8) * AT_STR + kb + t];
                qf[ks][2] = p[(g)     * AT_STR + kb + t + 4];
                qf[ks][3] = p[(g + 8) * AT_STR + kb + t + 4];
            }
        }
        __syncthreads();   // Ps now reusable for P tiles

        float o[8][4];
#pragma unroll
        for (int ni = 0; ni < 8; ni++)
#pragma unroll
            for (int r = 0; r < 4; r++) o[ni][r] = 0.f;

        float mA = -1e30f, mB = -1e30f, lA = 0.f, lB = 0.f;
        const int rowA = q0 + warp * 16 + g;
        const int warp_row0 = q0 + warp * 16;
        unsigned* Pw = Ps + (warp * 16) * AT_STR;

        for (int kt = 0; kt < n_tiles; kt++) {
            const int k0 = kt * 64;
            CP_WAIT0();
            __syncthreads();
            if (kt + 1 < n_tiles) issue_kv((kt + 1) * 64, (kt + 1) & 1);

            const unsigned* Ks = KsB + (kt & 1) * AT_KBUF;
            const unsigned* Vs = VsB + (kt & 1) * AT_KBUF;

            // ---- S = Q K^T ----
            float sacc[8][4];
#pragma unroll
            for (int ni = 0; ni < 8; ni++)
#pragma unroll
                for (int r = 0; r < 4; r++) sacc[ni][r] = 0.f;

#pragma unroll
            for (int ks = 0; ks < 8; ks++) {
                int kb = ks * 8;
                unsigned bf[8][2];
#pragma unroll
                for (int ni = 0; ni < 8; ni++) {
                    bf[ni][0] = Ks[(ni * 8 + g) * AT_STR + kb + t];
                    bf[ni][1] = Ks[(ni * 8 + g) * AT_STR + kb + t + 4];
                }
#pragma unroll
                for (int ni = 0; ni < 8; ni++)
                    mma_tf32(sacc[ni], qf[ks], bf[ni]);
            }

            // ---- scale by 1/sqrt(D) ----
#pragma unroll
            for (int ni = 0; ni < 8; ni++)
#pragma unroll
                for (int r = 0; r < 4; r++) sacc[ni][r] *= 0.125f;

            // ---- causal mask (warp-uniform outer condition) ----
            if (k0 + 63 > warp_row0) {
#pragma unroll
                for (int ni = 0; ni < 8; ni++) {
                    int c0 = k0 + ni * 8 + 2 * t;
                    if (c0     > rowA)     sacc[ni][0] = -1e30f;
                    if (c0 + 1 > rowA)     sacc[ni][1] = -1e30f;
                    if (c0     > rowA + 8) sacc[ni][2] = -1e30f;
                    if (c0 + 1 > rowA + 8) sacc[ni][3] = -1e30f;
                }
            }

            // ---- online softmax ----
            float mxA = -1e30f, mxB = -1e30f;
#pragma unroll
            for (int ni = 0; ni < 8; ni++) {
                mxA = fmaxf(mxA, fmaxf(sacc[ni][0], sacc[ni][1]));
                mxB = fmaxf(mxB, fmaxf(sacc[ni][2], sacc[ni][3]));
            }
            mxA = fmaxf(mxA, __shfl_xor_sync(0xffffffffu, mxA, 1));
            mxA = fmaxf(mxA, __shfl_xor_sync(0xffffffffu, mxA, 2));
            mxB = fmaxf(mxB, __shfl_xor_sync(0xffffffffu, mxB, 1));
            mxB = fmaxf(mxB, __shfl_xor_sync(0xffffffffu, mxB, 2));

            float mnA = fmaxf(mA, mxA), mnB = fmaxf(mB, mxB);
            float corrA = __expf(mA - mnA), corrB = __expf(mB - mnB);
            mA = mnA; mB = mnB;

            float sumA = 0.f, sumB = 0.f;
#pragma unroll
            for (int ni = 0; ni < 8; ni++) {
                float p0 = __expf(sacc[ni][0] - mA);
                float p1 = __expf(sacc[ni][1] - mA);
                float p2 = __expf(sacc[ni][2] - mB);
                float p3 = __expf(sacc[ni][3] - mB);
                sacc[ni][0] = p0; sacc[ni][1] = p1;
                sacc[ni][2] = p2; sacc[ni][3] = p3;
                sumA += p0 + p1; sumB += p2 + p3;
            }
            sumA += __shfl_xor_sync(0xffffffffu, sumA, 1);
            sumA += __shfl_xor_sync(0xffffffffu, sumA, 2);
            sumB += __shfl_xor_sync(0xffffffffu, sumB, 1);
            sumB += __shfl_xor_sync(0xffffffffu, sumB, 2);
            lA = lA * corrA + sumA;
            lB = lB * corrB + sumB;

#pragma unroll
            for (int ni = 0; ni < 8; ni++) {
                o[ni][0] *= corrA; o[ni][1] *= corrA;
                o[ni][2] *= corrB; o[ni][3] *= corrB;
            }

            // ---- P (tf32) -> warp-private smem: C-layout to A-layout ----
#pragma unroll
            for (int ni = 0; ni < 8; ni++) {
                uint2 ua, ub;
                ua.x = f2tf32(sacc[ni][0]); ua.y = f2tf32(sacc[ni][1]);
                ub.x = f2tf32(sacc[ni][2]); ub.y = f2tf32(sacc[ni][3]);
                *(uint2*)&Pw[(g)     * AT_STR + ni * 8 + 2 * t] = ua;
                *(uint2*)&Pw[(g + 8) * AT_STR + ni * 8 + 2 * t] = ub;
            }
            __syncwarp();

            // ---- O += P V ----
#pragma unroll
            for (int ks = 0; ks < 8; ks++) {
                int kb = ks * 8;
                unsigned pa[4];
                pa[0] = Pw[(g)     * AT_STR + kb + t];
                pa[1] = Pw[(g + 8) * AT_STR + kb + t];
                pa[2] = Pw[(g)     * AT_STR + kb + t + 4];
                pa[3] = Pw[(g + 8) * AT_STR + kb + t + 4];
                unsigned vb[8][2];
#pragma unroll
                for (int ni = 0; ni < 8; ni++) {
                    vb[ni][0] = Vs[(kb + t)     * AT_STR + ni * 8 + g];
                    vb[ni][1] = Vs[(kb + t + 4) * AT_STR + ni * 8 + g];
                }
#pragma unroll
                for (int ni = 0; ni < 8; ni++)
                    mma_tf32(o[ni], pa, vb[ni]);
            }
        }

        // ---- epilogue: normalize, store tf32 bits [B,S,E] ----
        const float invA = 1.f / lA, invB = 1.f / lB;
        unsigned* orow = out + (size_t)(b * Sc + rowA) * Ec + h * Dc;
#pragma unroll
        for (int ni = 0; ni < 8; ni++) {
            int c = ni * 8 + 2 * t;
            uint2 oa = make_uint2(f2tf32(o[ni][0] * invA), f2tf32(o[ni][1] * invA));
            uint2 ob = make_uint2(f2tf32(o[ni][2] * invB), f2tf32(o[ni][3] * invB));
            *(uint2*)(orow + c) = oa;
            *(uint2*)(orow + (size_t)8 * Ec + c) = ob;
        }
    }
}

// ---------------------------------------------------------------------------
extern "C" void kernel_launch(void* const* d_in, const int* in_sizes, int n_in,
                              void* d_out, int out_size)
{
    const float* x  = (const float*)d_in[0];   // hidden_states [B,S,E]
    const float* wa = (const float*)d_in[1];   // c_attn_w [E,3E]
    const float* ba = (const float*)d_in[2];   // c_attn_b [3E]
    const float* wp = (const float*)d_in[3];   // c_proj_w [E,E]
    const float* bp = (const float*)d_in[4];   // c_proj_b [E]
    float* out = (float*)d_out;

    unsigned *xc, *wac, *wpc, *qkv, *att;
    cudaGetSymbolAddress((void**)&xc,  g_xc);
    cudaGetSymbolAddress((void**)&wac, g_wac);
    cudaGetSymbolAddress((void**)&wpc, g_wpc);
    cudaGetSymbolAddress((void**)&qkv, g_qkv);
    cudaGetSymbolAddress((void**)&att, g_att);

    cudaFuncSetAttribute(gemm_tc<true>,  cudaFuncAttributeMaxDynamicSharedMemorySize, GEMM_SMEM_BYTES);
    cudaFuncSetAttribute(gemm_tc<false>, cudaFuncAttributeMaxDynamicSharedMemorySize, GEMM_SMEM_BYTES);
    cudaFuncSetAttribute(attn_tc, cudaFuncAttributeMaxDynamicSharedMemorySize, ATT_SMEM_BYTES);

    // 0) pre-convert inputs to tf32 bits
    {
        int n4x = (M_TOK * Ec) / 4;
        int n4a = (Ec * 3 * Ec) / 4;
        int n4p = (Ec * Ec) / 4;
        cvt_tf32_kernel<<<n4x / 256, 256>>>((const float4*)x,  (uint4*)xc,  n4x);
        cvt_tf32_kernel<<<n4a / 256, 256>>>((const float4*)wa, (uint4*)wac, n4a);
        cvt_tf32_kernel<<<n4p / 256, 256>>>((const float4*)wp, (uint4*)wpc, n4p);
    }

    // 1) QKV projection -> tf32 bits
    gemm_tc<true><<<dim3((3 * Ec) / 128, M_TOK / 128), 256, GEMM_SMEM_BYTES>>>(
        xc, wac, ba, qkv, M_TOK, 3 * Ec, Ec);

    // 2) tensor-core causal attention (paired blocks, single balanced wave)
    attn_tc<<<dim3(Sc / 256, Hc, Bc), 256, ATT_SMEM_BYTES>>>(qkv, att);

    // 3) output projection -> fp32
    gemm_tc<false><<<dim3(Ec / 128, M_TOK / 128), 256, GEMM_SMEM_BYTES>>>(
        att, wpc, bp, out, M_TOK, Ec, Ec);
}

// round 7
// speedup vs baseline: 4.1559x; 1.0312x over previous
#include <cuda_runtime.h>
#include <cuda_bf16.h>
#include <cstdint>

// Problem constants
#define Bc 2
#define Sc 2048
#define Ec 1024
#define Hc 16
#define Dc 64
#define M_TOK (Bc * Sc)          // 4096 rows

// Scratch (tf32 bit patterns stored as unsigned)
__device__ unsigned g_xc [(size_t)M_TOK * Ec];        // hidden_states (tf32)
__device__ unsigned g_wac[(size_t)Ec * 3 * Ec];       // c_attn_w (tf32) [E][3E]
__device__ unsigned g_wpc[(size_t)Ec * Ec];           // c_proj_w (tf32) [E][E]
__device__ unsigned g_qkv[(size_t)M_TOK * 3 * Ec];    // qkv (tf32)
__device__ unsigned g_att[(size_t)M_TOK * Ec];        // attn out (tf32)

__device__ __forceinline__ unsigned f2tf32(float x) {
    unsigned r;
    asm("cvt.rna.tf32.f32 %0, %1;" : "=r"(r) : "f"(x));
    return r;
}

__device__ __forceinline__ void mma_tf32(float* d, const unsigned* a, const unsigned* b) {
    asm volatile(
        "mma.sync.aligned.m16n8k8.row.col.f32.tf32.tf32.f32 "
        "{%0,%1,%2,%3}, {%4,%5,%6,%7}, {%8,%9}, {%0,%1,%2,%3};"
        : "+f"(d[0]), "+f"(d[1]), "+f"(d[2]), "+f"(d[3])
        : "r"(a[0]), "r"(a[1]), "r"(a[2]), "r"(a[3]), "r"(b[0]), "r"(b[1]));
}

__device__ __forceinline__ void cp_async16(void* dst_smem, const void* src) {
    unsigned d = (unsigned)__cvta_generic_to_shared(dst_smem);
    asm volatile("cp.async.cg.shared.global [%0], [%1], 16;\n" :: "r"(d), "l"(src));
}
#define CP_COMMIT() asm volatile("cp.async.commit_group;\n" ::: "memory")
#define CP_WAIT0()  asm volatile("cp.async.wait_group 0;\n" ::: "memory")
#define CP_WAIT1()  asm volatile("cp.async.wait_group 1;\n" ::: "memory")

// ---------------------------------------------------------------------------
// fused fp32 -> tf32 bit convert for all three inputs (one launch)
// ---------------------------------------------------------------------------
__global__ __launch_bounds__(256)
void cvt3_kernel(const float4* __restrict__ s0, uint4* __restrict__ d0, int n0,
                 const float4* __restrict__ s1, uint4* __restrict__ d1, int n1,
                 const float4* __restrict__ s2, uint4* __restrict__ d2, int n2)
{
    int i = blockIdx.x * blockDim.x + threadIdx.x;
    const float4* s; uint4* d; int j;
    if (i < n0)            { s = s0; d = d0; j = i; }
    else if (i < n0 + n1)  { s = s1; d = d1; j = i - n0; }
    else if (i < n0+n1+n2) { s = s2; d = d2; j = i - n0 - n1; }
    else return;
    float4 v = s[j];
    uint4 u;
    u.x = f2tf32(v.x); u.y = f2tf32(v.y);
    u.z = f2tf32(v.z); u.w = f2tf32(v.w);
    d[j] = u;
}

// ---------------------------------------------------------------------------
// tf32 tensor-core GEMM + bias, 3-stage cp.async ring, 1 sync/iter.
// C[M,N] = A[M,K] @ B[K,N] + bias[N].  BM=BN=128, BK=32, 256 thr, warp 32x64.
// ---------------------------------------------------------------------------
#define AS_STRIDE 36
#define BS_STRIDE 136
#define AS_BUF (128 * AS_STRIDE)     // 4608 words
#define BS_BUF (32 * BS_STRIDE)      // 4352 words
#define GEMM_SMEM_BYTES ((3 * AS_BUF + 3 * BS_BUF) * 4)  // 107520

template<bool OUT_TF32>
__global__ __launch_bounds__(256, 2)
void gemm_tc(const unsigned* __restrict__ A, const unsigned* __restrict__ B,
             const float* __restrict__ bias, void* __restrict__ Cv,
             int M, int N, int K)
{
    extern __shared__ unsigned sm[];
    unsigned* As = sm;               // [3][128][36]
    unsigned* Bs = sm + 3 * AS_BUF;  // [3][32][136]

    const int tid  = threadIdx.x;
    const int warp = tid >> 5, lane = tid & 31;
    const int g = lane >> 2, t = lane & 3;
    const int wm = (warp >> 1) * 32;
    const int wn = (warp & 1) * 64;
    const int bm = blockIdx.y * 128;
    const int bn = blockIdx.x * 128;

    const int am  = tid >> 3;
    const int ak  = (tid & 7) * 4;
    const int bk  = tid >> 5;
    const int bn4 = (tid & 31) * 4;

    auto issue_tile = [&](int it) {
        const int buf = it % 3;
        unsigned* Ad = As + buf * AS_BUF;
        unsigned* Bd = Bs + buf * BS_BUF;
        const int k0 = it * 32;
#pragma unroll
        for (int i = 0; i < 4; i++) {
            cp_async16(&Ad[(am + i * 32) * AS_STRIDE + ak],
                       &A[(size_t)(bm + am + i * 32) * K + k0 + ak]);
            cp_async16(&Bd[(bk + i * 8) * BS_STRIDE + bn4],
                       &B[(size_t)(k0 + bk + i * 8) * N + bn + bn4]);
        }
        CP_COMMIT();
    };

    const int iters = K / 32;
    issue_tile(0);
    issue_tile(1);

    float acc[2][8][4];
#pragma unroll
    for (int mi = 0; mi < 2; mi++)
#pragma unroll
        for (int ni = 0; ni < 8; ni++)
#pragma unroll
            for (int r = 0; r < 4; r++) acc[mi][ni][r] = 0.f;

    for (int it = 0; it < iters; it++) {
        if (it + 1 < iters) { CP_WAIT1(); } else { CP_WAIT0(); }
        __syncthreads();
        if (it + 2 < iters) issue_tile(it + 2);

        const unsigned* Ac = As + (it % 3) * AS_BUF;
        const unsigned* Bc2 = Bs + (it % 3) * BS_BUF;

#pragma unroll
        for (int ks = 0; ks < 4; ks++) {
            const int kb = ks * 8;
            unsigned af[2][4];
#pragma unroll
            for (int mi = 0; mi < 2; mi++) {
                const unsigned* p = Ac + (wm + mi * 16) * AS_STRIDE;
                af[mi][0] = p[(g)     * AS_STRIDE + kb + t];
                af[mi][1] = p[(g + 8) * AS_STRIDE + kb + t];
                af[mi][2] = p[(g)     * AS_STRIDE + kb + t + 4];
                af[mi][3] = p[(g + 8) * AS_STRIDE + kb + t + 4];
            }
            unsigned bf[8][2];
#pragma unroll
            for (int ni = 0; ni < 8; ni++) {
                bf[ni][0] = Bc2[(kb + t)     * BS_STRIDE + wn + ni * 8 + g];
                bf[ni][1] = Bc2[(kb + t + 4) * BS_STRIDE + wn + ni * 8 + g];
            }
#pragma unroll
            for (int mi = 0; mi < 2; mi++)
#pragma unroll
                for (int ni = 0; ni < 8; ni++)
                    mma_tf32(acc[mi][ni], af[mi], bf[ni]);
        }
        // no trailing sync: the buffer written at it+2 was last read at it-1,
        // whose readers all passed this iteration's top barrier.
    }

#pragma unroll
    for (int mi = 0; mi < 2; mi++) {
        const int r0 = bm + wm + mi * 16 + g;
#pragma unroll
        for (int ni = 0; ni < 8; ni++) {
            const int c = bn + wn + ni * 8 + t * 2;
            const float b0 = bias[c], b1 = bias[c + 1];
            if (OUT_TF32) {
                unsigned* C = (unsigned*)Cv;
                uint2 o0 = make_uint2(f2tf32(acc[mi][ni][0] + b0), f2tf32(acc[mi][ni][1] + b1));
                uint2 o1 = make_uint2(f2tf32(acc[mi][ni][2] + b0), f2tf32(acc[mi][ni][3] + b1));
                *(uint2*)&C[(size_t)r0 * N + c] = o0;
                *(uint2*)&C[(size_t)(r0 + 8) * N + c] = o1;
            } else {
                float* C = (float*)Cv;
                float2 o0 = make_float2(acc[mi][ni][0] + b0, acc[mi][ni][1] + b1);
                float2 o1 = make_float2(acc[mi][ni][2] + b0, acc[mi][ni][3] + b1);
                *(float2*)&C[(size_t)r0 * N + c] = o0;
                *(float2*)&C[(size_t)(r0 + 8) * N + c] = o1;
            }
        }
    }
}

// ---------------------------------------------------------------------------
// Tensor-core flash attention, PAIRED query blocks (unchanged from round 5).
// Grid: (S/256, H, B) = 256 CTAs -> one balanced wave, 34 key-tiles per CTA.
// ---------------------------------------------------------------------------
#define AT_STR 72
#define AT_KBUF (64 * AT_STR)
#define AT_VS_OFF (2 * AT_KBUF)
#define AT_PS_OFF (4 * AT_KBUF)
#define ATT_SMEM_BYTES ((4 * AT_KBUF + 128 * AT_STR) * 4)  // 110592

__global__ __launch_bounds__(256, 2)
void attn_tc(const unsigned* __restrict__ qkv, unsigned* __restrict__ out)
{
    extern __shared__ unsigned sm[];
    unsigned* KsB = sm;
    unsigned* VsB = sm + AT_VS_OFF;
    unsigned* Ps  = sm + AT_PS_OFF;

    const int h  = blockIdx.y;
    const int b  = blockIdx.z;
    const int tid  = threadIdx.x;
    const int warp = tid >> 5, lane = tid & 31;
    const int g = lane >> 2, t = lane & 3;
    const int nqx = Sc / 128;                      // 16

    const unsigned* base = qkv + (size_t)b * Sc * (3 * Ec) + h * Dc;

    auto issue_kv = [&](int k0, int buf) {
        unsigned* Kd = KsB + buf * AT_KBUF;
        unsigned* Vd = VsB + buf * AT_KBUF;
#pragma unroll
        for (int i = 0; i < 4; i++) {
            int idx = tid + i * 256;
            int r = idx >> 4, c = (idx & 15) * 4;
            const unsigned* kp = base + (size_t)(k0 + r) * (3 * Ec) + Ec + c;
            cp_async16(&Kd[r * AT_STR + c], kp);
            cp_async16(&Vd[r * AT_STR + c], kp + Ec);
        }
        CP_COMMIT();
    };

    for (int pass = 0; pass < 2; pass++) {
        const int qx = pass ? (int)blockIdx.x : (nqx - 1 - (int)blockIdx.x);
        const int q0 = qx * 128;
        const int n_tiles = 2 * (qx + 1);

        __syncthreads();
        issue_kv(0, 0);

#pragma unroll
        for (int i = 0; i < 8; i++) {
            int idx = tid + i * 256;
            int row = idx >> 4;
            int c4  = (idx & 15) * 4;
            *(uint4*)&Ps[row * AT_STR + c4] =
                *(const uint4*)(base + (size_t)(q0 + row) * (3 * Ec) + c4);
        }
        __syncthreads();

        unsigned qf[8][4];
        {
            const unsigned* p = Ps + (warp * 16) * AT_STR;
#pragma unroll
            for (int ks = 0; ks < 8; ks++) {
                int kb = ks * 8;
                qf[ks][0] = p[(g)     * AT_STR + kb + t];
                qf[ks][1] = p[(g + 8) * AT_STR + kb + t];
                qf[ks][2] = p[(g)     * AT_STR + kb + t + 4];
                qf[ks][3] = p[(g + 8) * AT_STR + kb + t + 4];
            }
        }
        __syncthreads();

        float o[8][4];
#pragma unroll
        for (int ni = 0; ni < 8; ni++)
#pragma unroll
            for (int r = 0; r < 4; r++) o[ni][r] = 0.f;

        float mA = -1e30f, mB = -1e30f, lA = 0.f, lB = 0.f;
        const int rowA = q0 + warp * 16 + g;
        const int warp_row0 = q0 + warp * 16;
        unsigned* Pw = Ps + (warp * 16) * AT_STR;

        for (int kt = 0; kt < n_tiles; kt++) {
            const int k0 = kt * 64;
            CP_WAIT0();
            __syncthreads();
            if (kt + 1 < n_tiles) issue_kv((kt + 1) * 64, (kt + 1) & 1);

            const unsigned* Ks = KsB + (kt & 1) * AT_KBUF;
            const unsigned* Vs = VsB + (kt & 1) * AT_KBUF;

            float sacc[8][4];
#pragma unroll
            for (int ni = 0; ni < 8; ni++)
#pragma unroll
                for (int r = 0; r < 4; r++) sacc[ni][r] = 0.f;

#pragma unroll
            for (int ks = 0; ks < 8; ks++) {
                int kb = ks * 8;
                unsigned bf[8][2];
#pragma unroll
                for (int ni = 0; ni < 8; ni++) {
                    bf[ni][0] = Ks[(ni * 8 + g) * AT_STR + kb + t];
                    bf[ni][1] = Ks[(ni * 8 + g) * AT_STR + kb + t + 4];
                }
#pragma unroll
                for (int ni = 0; ni < 8; ni++)
                    mma_tf32(sacc[ni], qf[ks], bf[ni]);
            }

#pragma unroll
            for (int ni = 0; ni < 8; ni++)
#pragma unroll
                for (int r = 0; r < 4; r++) sacc[ni][r] *= 0.125f;

            if (k0 + 63 > warp_row0) {
#pragma unroll
                for (int ni = 0; ni < 8; ni++) {
                    int c0 = k0 + ni * 8 + 2 * t;
                    if (c0     > rowA)     sacc[ni][0] = -1e30f;
                    if (c0 + 1 > rowA)     sacc[ni][1] = -1e30f;
                    if (c0     > rowA + 8) sacc[ni][2] = -1e30f;
                    if (c0 + 1 > rowA + 8) sacc[ni][3] = -1e30f;
                }
            }

            float mxA = -1e30f, mxB = -1e30f;
#pragma unroll
            for (int ni = 0; ni < 8; ni++) {
                mxA = fmaxf(mxA, fmaxf(sacc[ni][0], sacc[ni][1]));
                mxB = fmaxf(mxB, fmaxf(sacc[ni][2], sacc[ni][3]));
            }
            mxA = fmaxf(mxA, __shfl_xor_sync(0xffffffffu, mxA, 1));
            mxA = fmaxf(mxA, __shfl_xor_sync(0xffffffffu, mxA, 2));
            mxB = fmaxf(mxB, __shfl_xor_sync(0xffffffffu, mxB, 1));
            mxB = fmaxf(mxB, __shfl_xor_sync(0xffffffffu, mxB, 2));

            float mnA = fmaxf(mA, mxA), mnB = fmaxf(mB, mxB);
            float corrA = __expf(mA - mnA), corrB = __expf(mB - mnB);
            mA = mnA; mB = mnB;

            float sumA = 0.f, sumB = 0.f;
#pragma unroll
            for (int ni = 0; ni < 8; ni++) {
                float p0 = __expf(sacc[ni][0] - mA);
                float p1 = __expf(sacc[ni][1] - mA);
                float p2 = __expf(sacc[ni][2] - mB);
                float p3 = __expf(sacc[ni][3] - mB);
                sacc[ni][0] = p0; sacc[ni][1] = p1;
                sacc[ni][2] = p2; sacc[ni][3] = p3;
                sumA += p0 + p1; sumB += p2 + p3;
            }
            sumA += __shfl_xor_sync(0xffffffffu, sumA, 1);
            sumA += __shfl_xor_sync(0xffffffffu, sumA, 2);
            sumB += __shfl_xor_sync(0xffffffffu, sumB, 1);
            sumB += __shfl_xor_sync(0xffffffffu, sumB, 2);
            lA = lA * corrA + sumA;
            lB = lB * corrB + sumB;

#pragma unroll
            for (int ni = 0; ni < 8; ni++) {
                o[ni][0] *= corrA; o[ni][1] *= corrA;
                o[ni][2] *= corrB; o[ni][3] *= corrB;
            }

#pragma unroll
            for (int ni = 0; ni < 8; ni++) {
                uint2 ua, ub;
                ua.x = f2tf32(sacc[ni][0]); ua.y = f2tf32(sacc[ni][1]);
                ub.x = f2tf32(sacc[ni][2]); ub.y = f2tf32(sacc[ni][3]);
                *(uint2*)&Pw[(g)     * AT_STR + ni * 8 + 2 * t] = ua;
                *(uint2*)&Pw[(g + 8) * AT_STR + ni * 8 + 2 * t] = ub;
            }
            __syncwarp();

#pragma unroll
            for (int ks = 0; ks < 8; ks++) {
                int kb = ks * 8;
                unsigned pa[4];
                pa[0] = Pw[(g)     * AT_STR + kb + t];
                pa[1] = Pw[(g + 8) * AT_STR + kb + t];
                pa[2] = Pw[(g)     * AT_STR + kb + t + 4];
                pa[3] = Pw[(g + 8) * AT_STR + kb + t + 4];
                unsigned vb[8][2];
#pragma unroll
                for (int ni = 0; ni < 8; ni++) {
                    vb[ni][0] = Vs[(kb + t)     * AT_STR + ni * 8 + g];
                    vb[ni][1] = Vs[(kb + t + 4) * AT_STR + ni * 8 + g];
                }
#pragma unroll
                for (int ni = 0; ni < 8; ni++)
                    mma_tf32(o[ni], pa, vb[ni]);
            }
        }

        const float invA = 1.f / lA, invB = 1.f / lB;
        unsigned* orow = out + (size_t)(b * Sc + rowA) * Ec + h * Dc;
#pragma unroll
        for (int ni = 0; ni < 8; ni++) {
            int c = ni * 8 + 2 * t;
            uint2 oa = make_uint2(f2tf32(o[ni][0] * invA), f2tf32(o[ni][1] * invA));
            uint2 ob = make_uint2(f2tf32(o[ni][2] * invB), f2tf32(o[ni][3] * invB));
            *(uint2*)(orow + c) = oa;
            *(uint2*)(orow + (size_t)8 * Ec + c) = ob;
        }
    }
}

// ---------------------------------------------------------------------------
extern "C" void kernel_launch(void* const* d_in, const int* in_sizes, int n_in,
                              void* d_out, int out_size)
{
    const float* x  = (const float*)d_in[0];   // hidden_states [B,S,E]
    const float* wa = (const float*)d_in[1];   // c_attn_w [E,3E]
    const float* ba = (const float*)d_in[2];   // c_attn_b [3E]
    const float* wp = (const float*)d_in[3];   // c_proj_w [E,E]
    const float* bp = (const float*)d_in[4];   // c_proj_b [E]
    float* out = (float*)d_out;

    unsigned *xc, *wac, *wpc, *qkv, *att;
    cudaGetSymbolAddress((void**)&xc,  g_xc);
    cudaGetSymbolAddress((void**)&wac, g_wac);
    cudaGetSymbolAddress((void**)&wpc, g_wpc);
    cudaGetSymbolAddress((void**)&qkv, g_qkv);
    cudaGetSymbolAddress((void**)&att, g_att);

    cudaFuncSetAttribute(gemm_tc<true>,  cudaFuncAttributeMaxDynamicSharedMemorySize, GEMM_SMEM_BYTES);
    cudaFuncSetAttribute(gemm_tc<false>, cudaFuncAttributeMaxDynamicSharedMemorySize, GEMM_SMEM_BYTES);
    cudaFuncSetAttribute(attn_tc, cudaFuncAttributeMaxDynamicSharedMemorySize, ATT_SMEM_BYTES);

    // 0) pre-convert all inputs to tf32 bits in ONE launch
    {
        int n0 = (M_TOK * Ec) / 4;             // 1048576
        int n1 = (Ec * 3 * Ec) / 4;            // 786432
        int n2 = (Ec * Ec) / 4;                // 262144
        int total = n0 + n1 + n2;
        cvt3_kernel<<<(total + 255) / 256, 256>>>(
            (const float4*)x,  (uint4*)xc,  n0,
            (const float4*)wa, (uint4*)wac, n1,
            (const float4*)wp, (uint4*)wpc, n2);
    }

    // 1) QKV projection -> tf32 bits
    gemm_tc<true><<<dim3((3 * Ec) / 128, M_TOK / 128), 256, GEMM_SMEM_BYTES>>>(
        xc, wac, ba, qkv, M_TOK, 3 * Ec, Ec);

    // 2) tensor-core causal attention (paired blocks, single balanced wave)
    attn_tc<<<dim3(Sc / 256, Hc, Bc), 256, ATT_SMEM_BYTES>>>(qkv, att);

    // 3) output projection -> fp32
    gemm_tc<false><<<dim3(Ec / 128, M_TOK / 128), 256, GEMM_SMEM_BYTES>>>(
        att, wpc, bp, out, M_TOK, Ec, Ec);
}

// round 8
// speedup vs baseline: 7.7558x; 1.8662x over previous
#include <cuda_runtime.h>
#include <cuda_fp16.h>
#include <cstdint>

// Problem constants
#define Bc 2
#define Sc 2048
#define Ec 1024
#define Hc 16
#define Dc 64
#define M_TOK (Bc * Sc)          // 4096 rows

// Scratch (fp16 payloads packed in unsigned words)
__device__ unsigned g_xc [(size_t)M_TOK * Ec / 2];        // hidden_states fp16 [M][E]
__device__ unsigned g_wac[(size_t)3 * Ec * Ec / 2];       // c_attn_w^T fp16 [3E][E]
__device__ unsigned g_wpc[(size_t)Ec * Ec / 2];           // c_proj_w^T fp16 [E][E]
__device__ unsigned g_qkv[(size_t)M_TOK * 3 * Ec / 2];    // qkv fp16 [M][3E]
__device__ unsigned g_att[(size_t)M_TOK * Ec / 2];        // attn out fp16 [M][E]

__device__ __forceinline__ unsigned f2h2(float lo, float hi) {
    __half2 h = __floats2half2_rn(lo, hi);   // .x = lo (low 16 bits)
    return *reinterpret_cast<unsigned*>(&h);
}

__device__ __forceinline__ void mma_f16(float* d, const unsigned* a,
                                        unsigned b0, unsigned b1) {
    asm volatile(
        "mma.sync.aligned.m16n8k16.row.col.f32.f16.f16.f32 "
        "{%0,%1,%2,%3}, {%4,%5,%6,%7}, {%8,%9}, {%0,%1,%2,%3};"
        : "+f"(d[0]), "+f"(d[1]), "+f"(d[2]), "+f"(d[3])
        : "r"(a[0]), "r"(a[1]), "r"(a[2]), "r"(a[3]), "r"(b0), "r"(b1));
}

__device__ __forceinline__ void ldsm4(unsigned& r0, unsigned& r1, unsigned& r2,
                                      unsigned& r3, unsigned addr) {
    asm volatile("ldmatrix.sync.aligned.m8n8.x4.shared.b16 {%0,%1,%2,%3}, [%4];"
                 : "=r"(r0), "=r"(r1), "=r"(r2), "=r"(r3) : "r"(addr));
}
__device__ __forceinline__ void ldsm4t(unsigned& r0, unsigned& r1, unsigned& r2,
                                       unsigned& r3, unsigned addr) {
    asm volatile("ldmatrix.sync.aligned.m8n8.x4.trans.shared.b16 {%0,%1,%2,%3}, [%4];"
                 : "=r"(r0), "=r"(r1), "=r"(r2), "=r"(r3) : "r"(addr));
}

__device__ __forceinline__ void cp_async16(void* dst_smem, const void* src) {
    unsigned d = (unsigned)__cvta_generic_to_shared(dst_smem);
    asm volatile("cp.async.cg.shared.global [%0], [%1], 16;\n" :: "r"(d), "l"(src));
}
#define CP_COMMIT() asm volatile("cp.async.commit_group;\n" ::: "memory")
#define CP_WAIT0()  asm volatile("cp.async.wait_group 0;\n" ::: "memory")
#define CP_WAIT1()  asm volatile("cp.async.wait_group 1;\n" ::: "memory")

// ---------------------------------------------------------------------------
// fp32 -> fp16 convert (8 floats / thread -> one uint4 of 8 halves)
// ---------------------------------------------------------------------------
__global__ __launch_bounds__(256)
void cvt_h_kernel(const float4* __restrict__ s, uint4* __restrict__ d, int n8)
{
    int i = blockIdx.x * blockDim.x + threadIdx.x;
    if (i < n8) {
        float4 v0 = s[2 * i], v1 = s[2 * i + 1];
        uint4 u;
        u.x = f2h2(v0.x, v0.y); u.y = f2h2(v0.z, v0.w);
        u.z = f2h2(v1.x, v1.y); u.w = f2h2(v1.z, v1.w);
        d[i] = u;
    }
}

// fp32 [K][N] -> fp16 transposed [N][K] (words of half2)
__global__ __launch_bounds__(256)
void cvt_t_h_kernel(const float* __restrict__ src, unsigned* __restrict__ dst,
                    int K, int N)
{
    __shared__ float tile[32][33];
    int n0 = blockIdx.x * 32, k0 = blockIdx.y * 32;
    int tx = threadIdx.x & 31, ty = threadIdx.x >> 5;
#pragma unroll
    for (int i = ty; i < 32; i += 8)
        tile[i][tx] = src[(size_t)(k0 + i) * N + n0 + tx];
    __syncthreads();
#pragma unroll
    for (int i = ty; i < 32; i += 8)
        if (tx < 16)
            dst[((size_t)(n0 + i) * K + k0) / 2 + tx] =
                f2h2(tile[2 * tx][i], tile[2 * tx + 1][i]);
}

// ---------------------------------------------------------------------------
// fp16 tensor-core GEMM + bias: C[M,N] = A[M,K] @ Bt[N,K]^T + bias[N]
// BM=BN=128, BK=32 halves. 256 thr, warp tile 32x64. 3-stage cp.async ring.
// Smem rows 40 halves (80B): ldmatrix conflict-free (20j mod 32 tiles banks).
// ---------------------------------------------------------------------------
#define GH_BUF_W 2560                        // 128 rows * 20 words per buffer
#define GH_SMEM_BYTES (6 * GH_BUF_W * 4)     // 3 A + 3 B = 61440

template<bool OUT_F16>
__global__ __launch_bounds__(256, 2)
void gemm_h(const __half* __restrict__ A, const __half* __restrict__ Bt,
            const float* __restrict__ bias, void* __restrict__ Cv,
            int M, int N, int K)
{
    extern __shared__ unsigned sm[];

    const int tid  = threadIdx.x;
    const int warp = tid >> 5, lane = tid & 31;
    const int g = lane >> 2, t = lane & 3;
    const int wm = (warp >> 1) * 32;
    const int wn = (warp & 1) * 64;
    const int bm = blockIdx.y * 128;
    const int bn = blockIdx.x * 128;
    const int j = lane & 7, sel = lane >> 3;

    const unsigned smem_b = (unsigned)__cvta_generic_to_shared(sm);
    // ldmatrix lane-base addresses (A-style for A, B-style for B)
    const unsigned a_lane = smem_b +
        ((wm + (sel & 1) * 8 + j) * 40 + (sel >> 1) * 8) * 2;
    const unsigned b_lane = smem_b + 30720 +
        ((wn + (sel >> 1) * 8 + j) * 40 + (sel & 1) * 8) * 2;

    auto issue_tile = [&](int it) {
        const int buf = it % 3;
        const int k0 = it * 32;
        unsigned* Ad = sm + buf * GH_BUF_W;
        unsigned* Bd = sm + 3 * GH_BUF_W + buf * GH_BUF_W;
#pragma unroll
        for (int i = 0; i < 2; i++) {
            int idx = tid + i * 256;         // 0..511
            int row = idx >> 2, ch = idx & 3;
            cp_async16(&Ad[row * 20 + ch * 4],
                       A + (size_t)(bm + row) * K + k0 + ch * 8);
            cp_async16(&Bd[row * 20 + ch * 4],
                       Bt + (size_t)(bn + row) * K + k0 + ch * 8);
        }
        CP_COMMIT();
    };

    const int iters = K / 32;
    issue_tile(0);
    issue_tile(1);

    float acc[2][8][4];
#pragma unroll
    for (int mi = 0; mi < 2; mi++)
#pragma unroll
        for (int ni = 0; ni < 8; ni++)
#pragma unroll
            for (int r = 0; r < 4; r++) acc[mi][ni][r] = 0.f;

    for (int it = 0; it < iters; it++) {
        if (it + 1 < iters) { CP_WAIT1(); } else { CP_WAIT0(); }
        __syncthreads();
        if (it + 2 < iters) issue_tile(it + 2);

        const unsigned boff = (unsigned)((it % 3) * GH_BUF_W * 4);

#pragma unroll
        for (int ks = 0; ks < 2; ks++) {
            unsigned af[2][4];
            ldsm4(af[0][0], af[0][1], af[0][2], af[0][3], a_lane + boff + ks * 32);
            ldsm4(af[1][0], af[1][1], af[1][2], af[1][3],
                  a_lane + boff + 1280 + ks * 32);
#pragma unroll
            for (int np = 0; np < 4; np++) {
                unsigned b0, b1, b2, b3;
                ldsm4(b0, b1, b2, b3, b_lane + boff + np * 1280 + ks * 32);
                mma_f16(acc[0][2 * np],     af[0], b0, b1);
                mma_f16(acc[0][2 * np + 1], af[0], b2, b3);
                mma_f16(acc[1][2 * np],     af[1], b0, b1);
                mma_f16(acc[1][2 * np + 1], af[1], b2, b3);
            }
        }
    }

#pragma unroll
    for (int mi = 0; mi < 2; mi++) {
        const int r0 = bm + wm + mi * 16 + g;
#pragma unroll
        for (int ni = 0; ni < 8; ni++) {
            const int c = bn + wn + ni * 8 + t * 2;
            const float b0 = bias[c], b1 = bias[c + 1];
            if (OUT_F16) {
                unsigned* C = (unsigned*)Cv;
                C[((size_t)r0 * N + c) / 2] =
                    f2h2(acc[mi][ni][0] + b0, acc[mi][ni][1] + b1);
                C[((size_t)(r0 + 8) * N + c) / 2] =
                    f2h2(acc[mi][ni][2] + b0, acc[mi][ni][3] + b1);
            } else {
                float* C = (float*)Cv;
                *(float2*)&C[(size_t)r0 * N + c] =
                    make_float2(acc[mi][ni][0] + b0, acc[mi][ni][1] + b1);
                *(float2*)&C[(size_t)(r0 + 8) * N + c] =
                    make_float2(acc[mi][ni][2] + b0, acc[mi][ni][3] + b1);
            }
        }
    }
}

// ---------------------------------------------------------------------------
// fp16 flash attention, paired query blocks (one balanced wave).
// Grid (S/256, H, B) = 256 CTAs, 256 thr, warp owns 16 query rows.
// Smem halves (stride 72): Ks[2][64][72], Vs[2][64][72], Qs[128][72] = 55296 B.
// P never hits smem: C-frags repacked to fp16 A-frags. V via ldmatrix.trans.
// ---------------------------------------------------------------------------
#define AH_KBYTES 9216                       // one K or V buffer (64*72*2)
#define AH_V_OFF  18432
#define AH_Q_OFF  36864
#define AH_SMEM_BYTES 55296

__global__ __launch_bounds__(256, 2)
void attn_h(const __half* __restrict__ qkv, unsigned* __restrict__ out)
{
    extern __shared__ unsigned sm[];

    const int h  = blockIdx.y;
    const int b  = blockIdx.z;
    const int tid  = threadIdx.x;
    const int warp = tid >> 5, lane = tid & 31;
    const int g = lane >> 2, t = lane & 3;
    const int j = lane & 7, sel = lane >> 3;
    const int nqx = Sc / 128;                // 16

    const __half* base = qkv + (size_t)b * Sc * (3 * Ec) + h * Dc;
    const unsigned smem_b = (unsigned)__cvta_generic_to_shared(sm);

    // ldmatrix lane bases
    const unsigned q_lane = smem_b + AH_Q_OFF +
        ((warp * 16 + (sel & 1) * 8 + j) * 72 + (sel >> 1) * 8) * 2;   // A-style
    const unsigned k_lane = smem_b +
        (((sel >> 1) * 8 + j) * 72 + (sel & 1) * 8) * 2;               // B-style
    const unsigned v_lane = smem_b + AH_V_OFF +
        (((sel & 1) * 8 + j) * 72 + (sel >> 1) * 8) * 2;               // A-style (trans)

    auto issue_kv = [&](int k0, int buf) {
        unsigned* Kd = sm + (buf * AH_KBYTES) / 4;
        unsigned* Vd = sm + (AH_V_OFF + buf * AH_KBYTES) / 4;
#pragma unroll
        for (int i = 0; i < 4; i++) {
            int idx = tid + i * 256;          // 0..1023
            int vsel = idx >> 9;              // 0:K 1:V
            int r = (idx >> 3) & 63, ch = idx & 7;
            const __half* src = base + (size_t)(k0 + r) * (3 * Ec)
                                + Ec * (1 + vsel) + ch * 8;
            unsigned* dst = (vsel ? Vd : Kd) + (r * 72 + ch * 8) / 2;
            cp_async16(dst, src);
        }
        CP_COMMIT();
    };

    const unsigned* qkv_w = (const unsigned*)base;

    for (int pass = 0; pass < 2; pass++) {
        const int qx = pass ? (int)blockIdx.x : (nqx - 1 - (int)blockIdx.x);
        const int q0 = qx * 128;
        const int n_tiles = 2 * (qx + 1);

        __syncthreads();                      // previous pass's smem readers done
        issue_kv(0, 0);

        // stage Q tile (fp16) into smem
        unsigned* Qs = sm + AH_Q_OFF / 4;
#pragma unroll
        for (int i = 0; i < 4; i++) {
            int idx = tid + i * 256;          // 0..1023
            int row = idx >> 3, ch = idx & 7;
            *(uint4*)&Qs[row * 36 + ch * 4] =
                *(const uint4*)(qkv_w + (size_t)(q0 + row) * 1536 + ch * 4);
        }
        __syncthreads();

        unsigned qf[4][4];
#pragma unroll
        for (int ks = 0; ks < 4; ks++)
            ldsm4(qf[ks][0], qf[ks][1], qf[ks][2], qf[ks][3], q_lane + ks * 32);
        // no further sync needed: Qs untouched for rest of pass

        float o[8][4];
#pragma unroll
        for (int ni = 0; ni < 8; ni++)
#pragma unroll
            for (int r = 0; r < 4; r++) o[ni][r] = 0.f;

        float mA = -1e30f, mB = -1e30f, lA = 0.f, lB = 0.f;
        const int rowA = q0 + warp * 16 + g;
        const int warp_row0 = q0 + warp * 16;

        for (int kt = 0; kt < n_tiles; kt++) {
            const int k0 = kt * 64;
            CP_WAIT0();
            __syncthreads();
            if (kt + 1 < n_tiles) issue_kv((kt + 1) * 64, (kt + 1) & 1);

            const unsigned kvoff = (unsigned)((kt & 1) * AH_KBYTES);

            // ---- S = Q K^T ----
            float sacc[8][4];
#pragma unroll
            for (int ni = 0; ni < 8; ni++)
#pragma unroll
                for (int r = 0; r < 4; r++) sacc[ni][r] = 0.f;

#pragma unroll
            for (int ks = 0; ks < 4; ks++) {
#pragma unroll
                for (int np = 0; np < 4; np++) {
                    unsigned b0, b1, b2, b3;
                    ldsm4(b0, b1, b2, b3,
                          k_lane + kvoff + np * 2304 + ks * 32);
                    mma_f16(sacc[2 * np],     qf[ks], b0, b1);
                    mma_f16(sacc[2 * np + 1], qf[ks], b2, b3);
                }
            }

            // ---- scale by 1/sqrt(D) ----
#pragma unroll
            for (int ni = 0; ni < 8; ni++)
#pragma unroll
                for (int r = 0; r < 4; r++) sacc[ni][r] *= 0.125f;

            // ---- causal mask (warp-uniform outer condition) ----
            if (k0 + 63 > warp_row0) {
#pragma unroll
                for (int ni = 0; ni < 8; ni++) {
                    int c0 = k0 + ni * 8 + 2 * t;
                    if (c0     > rowA)     sacc[ni][0] = -1e30f;
                    if (c0 + 1 > rowA)     sacc[ni][1] = -1e30f;
                    if (c0     > rowA + 8) sacc[ni][2] = -1e30f;
                    if (c0 + 1 > rowA + 8) sacc[ni][3] = -1e30f;
                }
            }

            // ---- online softmax ----
            float mxA = -1e30f, mxB = -1e30f;
#pragma unroll
            for (int ni = 0; ni < 8; ni++) {
                mxA = fmaxf(mxA, fmaxf(sacc[ni][0], sacc[ni][1]));
                mxB = fmaxf(mxB, fmaxf(sacc[ni][2], sacc[ni][3]));
            }
            mxA = fmaxf(mxA, __shfl_xor_sync(0xffffffffu, mxA, 1));
            mxA = fmaxf(mxA, __shfl_xor_sync(0xffffffffu, mxA, 2));
            mxB = fmaxf(mxB, __shfl_xor_sync(0xffffffffu, mxB, 1));
            mxB = fmaxf(mxB, __shfl_xor_sync(0xffffffffu, mxB, 2));

            float mnA = fmaxf(mA, mxA), mnB = fmaxf(mB, mxB);
            float corrA = __expf(mA - mnA), corrB = __expf(mB - mnB);
            mA = mnA; mB = mnB;

            float sumA = 0.f, sumB = 0.f;
#pragma unroll
            for (int ni = 0; ni < 8; ni++) {
                float p0 = __expf(sacc[ni][0] - mA);
                float p1 = __expf(sacc[ni][1] - mA);
                float p2 = __expf(sacc[ni][2] - mB);
                float p3 = __expf(sacc[ni][3] - mB);
                sacc[ni][0] = p0; sacc[ni][1] = p1;
                sacc[ni][2] = p2; sacc[ni][3] = p3;
                sumA += p0 + p1; sumB += p2 + p3;
            }
            sumA += __shfl_xor_sync(0xffffffffu, sumA, 1);
            sumA += __shfl_xor_sync(0xffffffffu, sumA, 2);
            sumB += __shfl_xor_sync(0xffffffffu, sumB, 1);
            sumB += __shfl_xor_sync(0xffffffffu, sumB, 2);
            lA = lA * corrA + sumA;
            lB = lB * corrB + sumB;

#pragma unroll
            for (int ni = 0; ni < 8; ni++) {
                o[ni][0] *= corrA; o[ni][1] *= corrA;
                o[ni][2] *= corrB; o[ni][3] *= corrB;
            }

            // ---- O += P V : P repacked in registers, V via ldmatrix.trans ----
#pragma unroll
            for (int pk = 0; pk < 4; pk++) {
                unsigned pa[4];
                pa[0] = f2h2(sacc[2 * pk][0],     sacc[2 * pk][1]);
                pa[1] = f2h2(sacc[2 * pk][2],     sacc[2 * pk][3]);
                pa[2] = f2h2(sacc[2 * pk + 1][0], sacc[2 * pk + 1][1]);
                pa[3] = f2h2(sacc[2 * pk + 1][2], sacc[2 * pk + 1][3]);
#pragma unroll
                for (int fb = 0; fb < 4; fb++) {
                    unsigned v0, v1, v2, v3;
                    ldsm4t(v0, v1, v2, v3,
                           v_lane + kvoff + pk * 2304 + fb * 32);
                    mma_f16(o[2 * fb],     pa, v0, v1);
                    mma_f16(o[2 * fb + 1], pa, v2, v3);
                }
            }
        }

        // ---- epilogue: normalize, store fp16 [B,S,E] ----
        const float invA = 1.f / lA, invB = 1.f / lB;
        unsigned* orow = out + ((size_t)(b * Sc + rowA) * Ec + h * Dc) / 2;
#pragma unroll
        for (int ni = 0; ni < 8; ni++) {
            int cw = ni * 4 + t;                       // word index of col pair
            orow[cw] = f2h2(o[ni][0] * invA, o[ni][1] * invA);
            orow[cw + 8 * (Ec / 2)] = f2h2(o[ni][2] * invB, o[ni][3] * invB);
        }
    }
}

// ---------------------------------------------------------------------------
extern "C" void kernel_launch(void* const* d_in, const int* in_sizes, int n_in,
                              void* d_out, int out_size)
{
    const float* x  = (const float*)d_in[0];   // hidden_states [B,S,E]
    const float* wa = (const float*)d_in[1];   // c_attn_w [E,3E]
    const float* ba = (const float*)d_in[2];   // c_attn_b [3E]
    const float* wp = (const float*)d_in[3];   // c_proj_w [E,E]
    const float* bp = (const float*)d_in[4];   // c_proj_b [E]
    float* out = (float*)d_out;

    unsigned *xc, *wac, *wpc, *qkv, *att;
    cudaGetSymbolAddress((void**)&xc,  g_xc);
    cudaGetSymbolAddress((void**)&wac, g_wac);
    cudaGetSymbolAddress((void**)&wpc, g_wpc);
    cudaGetSymbolAddress((void**)&qkv, g_qkv);
    cudaGetSymbolAddress((void**)&att, g_att);

    cudaFuncSetAttribute(gemm_h<true>,  cudaFuncAttributeMaxDynamicSharedMemorySize, GH_SMEM_BYTES);
    cudaFuncSetAttribute(gemm_h<false>, cudaFuncAttributeMaxDynamicSharedMemorySize, GH_SMEM_BYTES);
    cudaFuncSetAttribute(attn_h, cudaFuncAttributeMaxDynamicSharedMemorySize, AH_SMEM_BYTES);

    // 0) pre-convert: x -> fp16; weights -> fp16 transposed [N][K]
    {
        int n8 = (M_TOK * Ec) / 8;
        cvt_h_kernel<<<(n8 + 255) / 256, 256>>>((const float4*)x, (uint4*)xc, n8);
        cvt_t_h_kernel<<<dim3((3 * Ec) / 32, Ec / 32), 256>>>(wa, wac, Ec, 3 * Ec);
        cvt_t_h_kernel<<<dim3(Ec / 32, Ec / 32), 256>>>(wp, wpc, Ec, Ec);
    }

    // 1) QKV projection -> fp16
    gemm_h<true><<<dim3((3 * Ec) / 128, M_TOK / 128), 256, GH_SMEM_BYTES>>>(
        (const __half*)xc, (const __half*)wac, ba, qkv, M_TOK, 3 * Ec, Ec);

    // 2) fp16 flash attention (paired blocks, single balanced wave) -> fp16
    attn_h<<<dim3(Sc / 256, Hc, Bc), 256, AH_SMEM_BYTES>>>(
        (const __half*)qkv, att);

    // 3) output projection -> fp32
    gemm_h<false><<<dim3(Ec / 128, M_TOK / 128), 256, GH_SMEM_BYTES>>>(
        (const __half*)att, (const __half*)wpc, bp, out, M_TOK, Ec, Ec);
}